// round 11
// baseline (speedup 1.0000x reference)
#include <cuda_runtime.h>
#include <math.h>

#define N_ 768
#define CS 384
#define CZ 128
#define NH 12
#define LINW 1152
#define CATW 2112
#define INF_ 100000.0f
#define NK_ ((size_t)N_ * N_)   // 589824

// ---------------- device scratch ----------------
__device__ float g_wpack[CS * LINW];
__device__ float g_bpack[LINW];
__device__ float g_pw[NH];
__device__ float g_lin[N_ * LINW];
__device__ float g_qops[NH * N_ * 32];
__device__ float g_kops[NH * N_ * 32];
__device__ float g_vops[NH * N_ * 40];
__device__ float g_L[NH * NK_];
__device__ float g_cat[N_ * CATW];
__device__ float g_part[3][N_ * CS];

// ---------------- f32x2 helpers ----------------
typedef unsigned long long u64;
__device__ __forceinline__ u64 pk2(float a, float b) {
  u64 r;
  asm("mov.b64 %0, {%1,%2};" : "=l"(r) : "f"(a), "f"(b));
  return r;
}
__device__ __forceinline__ void upk2(u64 v, float& a, float& b) {
  asm("mov.b64 {%0,%1}, %2;" : "=f"(a), "=f"(b) : "l"(v));
}
__device__ __forceinline__ void fma2(u64& d, u64 a, u64 b) {
  asm("fma.rn.f32x2 %0, %1, %2, %0;" : "+l"(d) : "l"(a), "l"(b));
}

// ---------------- pack weights ----------------
__global__ void k_pack(const float* wq, const float* wk, const float* wv,
                       const float* wqp, const float* wkp, const float* wvp,
                       const float* bq, const float* bk, const float* bv,
                       const float* bqp, const float* bkp, const float* bvp,
                       const float* hw) {
  int idx = blockIdx.x * 256 + threadIdx.x;
  if (idx < CS * LINW) {
    int i = idx / LINW, j = idx - i * LINW;
    float v;
    if (j < 192)       v = wq[i * 192 + j];
    else if (j < 384)  v = wk[i * 192 + j - 192];
    else if (j < 576)  v = wv[i * 192 + j - 384];
    else if (j < 720)  v = wqp[i * 144 + j - 576];
    else if (j < 864)  v = wkp[i * 144 + j - 720];
    else               v = wvp[i * 288 + j - 864];
    g_wpack[idx] = v;
  }
  if (idx < LINW) {
    int j = idx;
    float v;
    if (j < 192)       v = bq[j];
    else if (j < 384)  v = bk[j - 192];
    else if (j < 576)  v = bv[j - 384];
    else if (j < 720)  v = bqp[j - 576];
    else if (j < 864)  v = bkp[j - 720];
    else               v = bvp[j - 864];
    g_bpack[j] = v;
  }
  if (idx < NH) {
    float h = hw[idx];
    g_pw[idx] = 0.23570226039551584f * (fmaxf(h, 0.f) + log1pf(expf(-fabsf(h))));
  }
}

// ---------------- GEMM 1: g_lin = s @ wpack (768x1152, K=384), pipelined ----------------
__global__ __launch_bounds__(256) void k_gemm1(const float* __restrict__ A) {
  __shared__ float aT[16][68];
  __shared__ float bT[16][68];
  int m0 = blockIdx.x * 64, n0 = blockIdx.y * 64;
  int t = threadIdx.x;
  int mi = (t & 15) * 4, ni = (t >> 4) * 4;
  u64 c2[4][2] = {};
  float a_pf[4], b_pf[4];
#pragma unroll
  for (int j = 0; j < 4; ++j) {
    int e = t + j * 256;
    a_pf[j] = A[(m0 + (e >> 4)) * CS + (e & 15)];
    b_pf[j] = g_wpack[(e >> 6) * LINW + n0 + (e & 63)];
  }
  for (int kt = 0; kt < 24; ++kt) {
    __syncthreads();
#pragma unroll
    for (int j = 0; j < 4; ++j) {
      int e = t + j * 256;
      aT[e & 15][e >> 4] = a_pf[j];
      bT[e >> 6][e & 63] = b_pf[j];
    }
    if (kt + 1 < 24) {
      int k0 = (kt + 1) * 16;
#pragma unroll
      for (int j = 0; j < 4; ++j) {
        int e = t + j * 256;
        a_pf[j] = A[(m0 + (e >> 4)) * CS + k0 + (e & 15)];
        b_pf[j] = g_wpack[(k0 + (e >> 6)) * LINW + n0 + (e & 63)];
      }
    }
    __syncthreads();
#pragma unroll
    for (int kk = 0; kk < 16; ++kk) {
      float4 a = *(const float4*)&aT[kk][mi];
      float4 b = *(const float4*)&bT[kk][ni];
      u64 b0 = pk2(b.x, b.y), b1 = pk2(b.z, b.w);
      u64 a0 = pk2(a.x, a.x), a1 = pk2(a.y, a.y), a2 = pk2(a.z, a.z), a3 = pk2(a.w, a.w);
      fma2(c2[0][0], a0, b0); fma2(c2[0][1], a0, b1);
      fma2(c2[1][0], a1, b0); fma2(c2[1][1], a1, b1);
      fma2(c2[2][0], a2, b0); fma2(c2[2][1], a2, b1);
      fma2(c2[3][0], a3, b0); fma2(c2[3][1], a3, b1);
    }
  }
#pragma unroll
  for (int r = 0; r < 4; ++r)
#pragma unroll
    for (int j = 0; j < 2; ++j) {
      float lo, hi;
      upk2(c2[r][j], lo, hi);
      g_lin[(m0 + mi + r) * LINW + n0 + ni + 2 * j] = lo;
      g_lin[(m0 + mi + r) * LINW + n0 + ni + 2 * j + 1] = hi;
    }
}

// ---------------- GEMM 2: part[z] = cat @ w_o (768x384, K=2112 split 3), pipelined ----------------
__global__ __launch_bounds__(256) void k_gemm2(const float* __restrict__ B) {
  __shared__ float aT[16][68];
  __shared__ float bT[16][68];
  int m0 = blockIdx.x * 64, n0 = blockIdx.y * 64;
  int t = threadIdx.x;
  int mi = (t & 15) * 4, ni = (t >> 4) * 4;
  u64 c2[4][2] = {};
  int kbase = blockIdx.z * 44 * 16;
  float a_pf[4], b_pf[4];
#pragma unroll
  for (int j = 0; j < 4; ++j) {
    int e = t + j * 256;
    a_pf[j] = g_cat[(m0 + (e >> 4)) * CATW + kbase + (e & 15)];
    b_pf[j] = B[(kbase + (e >> 6)) * CS + n0 + (e & 63)];
  }
  for (int kt = 0; kt < 44; ++kt) {
    __syncthreads();
#pragma unroll
    for (int j = 0; j < 4; ++j) {
      int e = t + j * 256;
      aT[e & 15][e >> 4] = a_pf[j];
      bT[e >> 6][e & 63] = b_pf[j];
    }
    if (kt + 1 < 44) {
      int k0 = kbase + (kt + 1) * 16;
#pragma unroll
      for (int j = 0; j < 4; ++j) {
        int e = t + j * 256;
        a_pf[j] = g_cat[(m0 + (e >> 4)) * CATW + k0 + (e & 15)];
        b_pf[j] = B[(k0 + (e >> 6)) * CS + n0 + (e & 63)];
      }
    }
    __syncthreads();
#pragma unroll
    for (int kk = 0; kk < 16; ++kk) {
      float4 a = *(const float4*)&aT[kk][mi];
      float4 b = *(const float4*)&bT[kk][ni];
      u64 b0 = pk2(b.x, b.y), b1 = pk2(b.z, b.w);
      u64 a0 = pk2(a.x, a.x), a1 = pk2(a.y, a.y), a2 = pk2(a.z, a.z), a3 = pk2(a.w, a.w);
      fma2(c2[0][0], a0, b0); fma2(c2[0][1], a0, b1);
      fma2(c2[1][0], a1, b0); fma2(c2[1][1], a1, b1);
      fma2(c2[2][0], a2, b0); fma2(c2[2][1], a2, b1);
      fma2(c2[3][0], a3, b0); fma2(c2[3][1], a3, b1);
    }
  }
  float* outp = &g_part[blockIdx.z][0];
#pragma unroll
  for (int r = 0; r < 4; ++r)
#pragma unroll
    for (int j = 0; j < 2; ++j) {
      float lo, hi;
      upk2(c2[r][j], lo, hi);
      outp[(m0 + mi + r) * CS + n0 + ni + 2 * j] = lo;
      outp[(m0 + mi + r) * CS + n0 + ni + 2 * j + 1] = hi;
    }
}

// ---------------- projection epilogue per residue ----------------
__global__ __launch_bounds__(128) void k_proj(const float* __restrict__ rot,
                                              const float* __restrict__ trans) {
  __shared__ float s2[24];
  int q = blockIdx.x, t = threadIdx.x;
  const float* lin = g_lin + q * LINW;
  if (t < 24) s2[t] = 0.f;
  __syncthreads();
  float R[9], tr[3];
#pragma unroll
  for (int j = 0; j < 9; ++j) R[j] = __ldg(rot + q * 9 + j);
#pragma unroll
  for (int j = 0; j < 3; ++j) tr[j] = __ldg(trans + q * 3 + j);
  for (int i = t; i < 192; i += 128) {
    int h = i >> 4, c = i & 15;
    g_qops[(h * N_ + q) * 32 + c] = (lin[i] + g_bpack[i]) * 0.25f;
    g_kops[(h * N_ + q) * 32 + c] = lin[192 + i] + g_bpack[192 + i];
    g_vops[(h * N_ + q) * 40 + c] = lin[384 + i] + g_bpack[384 + i];
  }
  if (t < 96) {
    int which = t / 48;
    int i = t % 48;
    int h = i >> 2, p = i & 3;
    int base = 576 + which * 144 + h * 12;
    float lx = lin[base + p] + g_bpack[base + p];
    float ly = lin[base + 4 + p] + g_bpack[base + 4 + p];
    float lz = lin[base + 8 + p] + g_bpack[base + 8 + p];
    float gx = R[0] * lx + R[1] * ly + R[2] * lz + tr[0];
    float gy = R[3] * lx + R[4] * ly + R[5] * lz + tr[1];
    float gz = R[6] * lx + R[7] * ly + R[8] * lz + tr[2];
    float n2 = gx * gx + gy * gy + gz * gz;
    int o = (h * N_ + q) * 32 + 16 + p * 3;
    if (which == 0) {
      g_qops[o] = gx; g_qops[o + 1] = gy; g_qops[o + 2] = gz;
      atomicAdd(&s2[h], n2);
    } else {
      g_kops[o] = gx; g_kops[o + 1] = gy; g_kops[o + 2] = gz;
      atomicAdd(&s2[12 + h], n2);
    }
  }
  if (t < 96) {
    int h = t >> 3, p = t & 7;
    int base = 864 + h * 24;
    float lx = lin[base + p] + g_bpack[base + p];
    float ly = lin[base + 8 + p] + g_bpack[base + 8 + p];
    float lz = lin[base + 16 + p] + g_bpack[base + 16 + p];
    float gx = R[0] * lx + R[1] * ly + R[2] * lz + tr[0];
    float gy = R[3] * lx + R[4] * ly + R[5] * lz + tr[1];
    float gz = R[6] * lx + R[7] * ly + R[8] * lz + tr[2];
    int o = (h * N_ + q) * 40 + 16 + p * 3;
    g_vops[o] = gx; g_vops[o + 1] = gy; g_vops[o + 2] = gz;
  }
  __syncthreads();
  if (t < 12) {
    g_qops[(t * N_ + q) * 32 + 28] = s2[t];
    g_kops[(t * N_ + q) * 32 + 28] = s2[12 + t];
  }
}

// ---------------- pair bias (k_bias7, unchanged) ----------------
__global__ __launch_bounds__(128) void k_bias7(const float* __restrict__ z,
                                               const float* __restrict__ wb,
                                               const float* __restrict__ bb) {
  extern __shared__ u64 sm7[];
  u64* zb0 = sm7;
  u64* zb1 = sm7 + 16 * 257;
  u64* w2 = sm7 + 2 * 16 * 257;
  int t = threadIdx.x;
  for (int idx = t; idx < 1536; idx += 128) {
    int c = idx / 12, h = idx - c * 12;
    float w = __ldg(wb + c * 12 + h);
    w2[idx] = pk2(w, w);
  }
  size_t R0 = (size_t)blockIdx.x * 512;

  float4 vA[8], vB[8];
#pragma unroll
  for (int i = 0; i < 8; ++i) {
    int idx = t + i * 128;
    int rp = idx >> 2, j = idx & 3;
    const float* pA = z + (R0 + rp) * CZ + 4 * j;
    vA[i] = *(const float4*)pA;
    vB[i] = *(const float4*)(pA + 256 * CZ);
  }
#pragma unroll
  for (int i = 0; i < 8; ++i) {
    int idx = t + i * 128;
    int rp = idx >> 2, j = idx & 3;
    u64* d = zb0 + 4 * j * 257 + rp;
    d[0] = pk2(vA[i].x, vB[i].x);
    d[257] = pk2(vA[i].y, vB[i].y);
    d[514] = pk2(vA[i].z, vB[i].z);
    d[771] = pk2(vA[i].w, vB[i].w);
  }
  __syncthreads();

  u64 acc0[12] = {}, acc1[12] = {};
  for (int ch = 0; ch < 8; ++ch) {
    u64* cur = (ch & 1) ? zb1 : zb0;
    u64* nxt = (ch & 1) ? zb0 : zb1;
    if (ch < 7) {
#pragma unroll
      for (int i = 0; i < 8; ++i) {
        int idx = t + i * 128;
        int rp = idx >> 2, j = idx & 3;
        const float* pA = z + (R0 + rp) * CZ + (ch + 1) * 16 + 4 * j;
        vA[i] = *(const float4*)pA;
        vB[i] = *(const float4*)(pA + 256 * CZ);
      }
    }
    const u64* w2c = w2 + ch * 16 * 12;
#pragma unroll
    for (int cl = 0; cl < 16; ++cl) {
      u64 z0 = cur[cl * 257 + t];
      u64 z1 = cur[cl * 257 + t + 128];
      const u64* wr = w2c + cl * 12;
#pragma unroll
      for (int h = 0; h < 12; ++h) {
        u64 w = wr[h];
        fma2(acc0[h], z0, w);
        fma2(acc1[h], z1, w);
      }
    }
    if (ch < 7) {
#pragma unroll
      for (int i = 0; i < 8; ++i) {
        int idx = t + i * 128;
        int rp = idx >> 2, j = idx & 3;
        u64* d = nxt + 4 * j * 257 + rp;
        d[0] = pk2(vA[i].x, vB[i].x);
        d[257] = pk2(vA[i].y, vB[i].y);
        d[514] = pk2(vA[i].z, vB[i].z);
        d[771] = pk2(vA[i].w, vB[i].w);
      }
    }
    __syncthreads();
  }
#pragma unroll
  for (int h = 0; h < 12; ++h) {
    float bbh = __ldg(bb + h);
    float a, b, c, d;
    upk2(acc0[h], a, b);
    upk2(acc1[h], c, d);
    float* Lp = g_L + (size_t)h * NK_ + R0;
    Lp[t] = a + bbh;
    Lp[t + 256] = b + bbh;
    Lp[t + 128] = c + bbh;
    Lp[t + 384] = d + bbh;
  }
}

// ---------------- logits + softmax (in place on g_L) ----------------
__global__ __launch_bounds__(256) void k_logits(const float* __restrict__ mask) {
  __shared__ float ks[256 * 36];
  int t = threadIdx.x;
  int h = blockIdx.y;
  int Q0 = blockIdx.x * 16;
  int ql = t >> 4, s = t & 15;
  int q = Q0 + ql;
  const float* qop = g_qops + ((size_t)h * N_ + q) * 32;
  const u64* qop8 = (const u64*)qop;
  u64 qh_u[8], qp_u[6];
#pragma unroll
  for (int i = 0; i < 8; ++i) qh_u[i] = qop8[i];
#pragma unroll
  for (int i = 0; i < 6; ++i) qp_u[i] = qop8[8 + i];
  float q2 = qop[28];
  float pw = g_pw[h];
  float cb = -0.5f * pw * q2;
  float mq = __ldg(mask + q);
  const float* Lrow = g_L + ((size_t)h * N_ + q) * N_;
  float lg[48];
#pragma unroll
  for (int ch = 0; ch < 3; ++ch) {
    int k0 = ch * 256;
    __syncthreads();
#pragma unroll
    for (int i = 0; i < 8; ++i) {
      int idx = t + i * 256;
      int row = idx >> 3, f4 = idx & 7;
      *(float4*)(ks + row * 36 + f4 * 4) =
          *(const float4*)(g_kops + ((size_t)h * N_ + k0 + row) * 32 + f4 * 4);
    }
    __syncthreads();
#pragma unroll
    for (int jj = 0; jj < 16; ++jj) {
      int kl = s + 16 * jj;
      const u64* kr8 = (const u64*)(ks + kl * 36);
      u64 d2 = 0, e2 = 0;
#pragma unroll
      for (int i = 0; i < 8; ++i) fma2(d2, kr8[i], qh_u[i]);
#pragma unroll
      for (int i = 0; i < 6; ++i) fma2(e2, kr8[8 + i], qp_u[i]);
      float dlo, dhi, elo, ehi;
      upk2(d2, dlo, dhi);
      upk2(e2, elo, ehi);
      float k2s = ks[kl * 36 + 28];
      int k = k0 + kl;
      lg[ch * 16 + jj] = Lrow[k] + dlo + dhi + pw * (elo + ehi - 0.5f * k2s) + cb
                         + INF_ * (mq * __ldg(mask + k) - 1.f);
    }
  }
  float mx = -3.0e38f;
#pragma unroll
  for (int i = 0; i < 48; ++i) mx = fmaxf(mx, lg[i]);
  mx = fmaxf(mx, __shfl_xor_sync(0xffffffffu, mx, 1));
  mx = fmaxf(mx, __shfl_xor_sync(0xffffffffu, mx, 2));
  mx = fmaxf(mx, __shfl_xor_sync(0xffffffffu, mx, 4));
  mx = fmaxf(mx, __shfl_xor_sync(0xffffffffu, mx, 8));
  float sum = 0.f;
#pragma unroll
  for (int i = 0; i < 48; ++i) {
    float w = __expf(0.57735026919f * (lg[i] - mx));
    lg[i] = w;
    sum += w;
  }
  sum += __shfl_xor_sync(0xffffffffu, sum, 1);
  sum += __shfl_xor_sync(0xffffffffu, sum, 2);
  sum += __shfl_xor_sync(0xffffffffu, sum, 4);
  sum += __shfl_xor_sync(0xffffffffu, sum, 8);
  float inv = 1.f / sum;
  float* Lw = g_L + ((size_t)h * N_ + q) * N_;
#pragma unroll
  for (int ch = 0; ch < 3; ++ch)
#pragma unroll
    for (int jj = 0; jj < 16; ++jj)
      Lw[ch * 256 + s + 16 * jj] = lg[ch * 16 + jj] * inv;
}

// ---------------- o + o_pt + norms ----------------
__global__ __launch_bounds__(160) void k_out(const float* __restrict__ rot,
                                             const float* __restrict__ trans) {
  __shared__ float as[32 * 132];
  __shared__ float vs[128 * 44];
  __shared__ float os[32 * 40];
  int t = threadIdx.x;
  int h = blockIdx.y;
  int Q0 = blockIdx.x * 32;
  int q = t / 5, s = t - q * 5;
  u64 acc2[4] = {};
  for (int ch = 0; ch < 6; ++ch) {
    int k0 = ch * 128;
    __syncthreads();
    for (int idx = t; idx < 1024; idx += 160) {
      int qq = idx >> 5, f4 = idx & 31;
      *(float4*)(as + qq * 132 + f4 * 4) =
          *(const float4*)(g_L + ((size_t)h * N_ + Q0 + qq) * N_ + k0 + f4 * 4);
    }
    for (int idx = t; idx < 1280; idx += 160) {
      int row = idx / 10, f4 = idx - row * 10;
      *(float4*)(vs + row * 44 + f4 * 4) =
          *(const float4*)(g_vops + ((size_t)h * N_ + k0 + row) * 40 + f4 * 4);
    }
    __syncthreads();
#pragma unroll 4
    for (int kl = 0; kl < 128; ++kl) {
      float a = as[q * 132 + kl];
      u64 au = pk2(a, a);
      const u64* vp = (const u64*)(vs + kl * 44 + 8 * s);
      fma2(acc2[0], vp[0], au);
      fma2(acc2[1], vp[1], au);
      fma2(acc2[2], vp[2], au);
      fma2(acc2[3], vp[3], au);
    }
  }
#pragma unroll
  for (int i = 0; i < 4; ++i) {
    float lo, hi;
    upk2(acc2[i], lo, hi);
    os[q * 40 + 8 * s + 2 * i] = lo;
    os[q * 40 + 8 * s + 2 * i + 1] = hi;
  }
  __syncthreads();
  for (int idx = t; idx < 512; idx += 160) {
    int qq = idx >> 4, c = idx & 15;
    g_cat[(size_t)(Q0 + qq) * CATW + h * 16 + c] = os[qq * 40 + c];
  }
  for (int idx = t; idx < 256; idx += 160) {
    int qq = idx >> 3, p = idx & 7;
    int gq = Q0 + qq;
    float ex = os[qq * 40 + 16 + 3 * p] - __ldg(trans + gq * 3 + 0);
    float ey = os[qq * 40 + 17 + 3 * p] - __ldg(trans + gq * 3 + 1);
    float ez = os[qq * 40 + 18 + 3 * p] - __ldg(trans + gq * 3 + 2);
    const float* R = rot + gq * 9;
    float lx = __ldg(R + 0) * ex + __ldg(R + 3) * ey + __ldg(R + 6) * ez;
    float ly = __ldg(R + 1) * ex + __ldg(R + 4) * ey + __ldg(R + 7) * ez;
    float lz = __ldg(R + 2) * ex + __ldg(R + 5) * ey + __ldg(R + 8) * ez;
    float* cp = g_cat + (size_t)gq * CATW + 192 + h * 8 + p;
    cp[0] = lx;
    cp[96] = ly;
    cp[192] = lz;
    cp[288] = sqrtf(lx * lx + ly * ly + lz * lz + 1e-8f);
  }
}

// ---------------- o_pair: round-8 mapping + pre-duplicated u64 aT (no per-k movs) ----------------
__global__ __launch_bounds__(256) void k_opair(const float* __restrict__ z) {
  extern __shared__ u64 smo[];
  u64* aTd = smo;  // [768][12] duplicated attention weights, pk2(a,a)
  int t = threadIdx.x;
  int q = blockIdx.x;
  for (int idx = t; idx < 12 * N_; idx += 256) {
    int h = idx / N_;
    int kk = idx - h * N_;
    float a = g_L[((size_t)h * N_ + q) * N_ + kk];
    aTd[kk * 12 + h] = pk2(a, a);
  }
  __syncthreads();
  int c2 = (t & 63) * 2, kg = t >> 6;
  const float* zq = z + (size_t)q * N_ * CZ;
  u64 acc[12] = {};
#pragma unroll 4
  for (int k = kg; k < N_; k += 4) {
    u64 zd = *(const u64*)(zq + (size_t)k * CZ + c2);
    const ulonglong2* ar = (const ulonglong2*)(aTd + k * 12);  // 16B-aligned (96B row)
    ulonglong2 a01 = ar[0];
    ulonglong2 a23 = ar[1];
    ulonglong2 a45 = ar[2];
    ulonglong2 a67 = ar[3];
    ulonglong2 a89 = ar[4];
    ulonglong2 aAB = ar[5];
    fma2(acc[0], zd, a01.x);  fma2(acc[1], zd, a01.y);
    fma2(acc[2], zd, a23.x);  fma2(acc[3], zd, a23.y);
    fma2(acc[4], zd, a45.x);  fma2(acc[5], zd, a45.y);
    fma2(acc[6], zd, a67.x);  fma2(acc[7], zd, a67.y);
    fma2(acc[8], zd, a89.x);  fma2(acc[9], zd, a89.y);
    fma2(acc[10], zd, aAB.x); fma2(acc[11], zd, aAB.y);
  }
  __syncthreads();
  u64* buf = smo;  // [256][12]
#pragma unroll
  for (int h = 0; h < 12; ++h) buf[t * 12 + h] = acc[h];
  __syncthreads();
  for (int idx = t; idx < 1536; idx += 256) {
    int h = idx >> 7, c = idx & 127;
    float sum = 0.f;
#pragma unroll
    for (int g = 0; g < 4; ++g) {
      float lo, hi;
      upk2(buf[(g * 64 + (c >> 1)) * 12 + h], lo, hi);
      sum += (c & 1) ? hi : lo;
    }
    g_cat[(size_t)q * CATW + 576 + h * 128 + c] = sum;
  }
}

// ---------------- final add ----------------
__global__ void k_add(const float* __restrict__ bo, float* __restrict__ out) {
  int i = blockIdx.x * 256 + threadIdx.x;
  if (i < N_ * CS) {
    int col = i % CS;
    out[i] = g_part[0][i] + g_part[1][i] + g_part[2][i] + __ldg(bo + col);
  }
}

extern "C" void kernel_launch(void* const* d_in, const int* in_sizes, int n_in,
                              void* d_out, int out_size) {
  const float* s     = (const float*)d_in[0];
  const float* z     = (const float*)d_in[1];
  const float* rot   = (const float*)d_in[2];
  const float* trans = (const float*)d_in[3];
  const float* mask  = (const float*)d_in[4];
  const float* w_q   = (const float*)d_in[5];
  const float* b_q   = (const float*)d_in[6];
  const float* w_k   = (const float*)d_in[7];
  const float* b_k   = (const float*)d_in[8];
  const float* w_v   = (const float*)d_in[9];
  const float* b_v   = (const float*)d_in[10];
  const float* w_qp  = (const float*)d_in[11];
  const float* b_qp  = (const float*)d_in[12];
  const float* w_kp  = (const float*)d_in[13];
  const float* b_kp  = (const float*)d_in[14];
  const float* w_vp  = (const float*)d_in[15];
  const float* b_vp  = (const float*)d_in[16];
  const float* w_b   = (const float*)d_in[17];
  const float* b_b   = (const float*)d_in[18];
  const float* hw    = (const float*)d_in[19];
  const float* w_o   = (const float*)d_in[20];
  const float* b_o   = (const float*)d_in[21];
  float* out = (float*)d_out;

  const int BIAS_SMEM = (2 * 16 * 257 + 1536) * 8;  // 78080 bytes
  const int OPAIR_SMEM = 768 * 12 * 8;               // 73728 bytes

  static bool init_done = false;
  static cudaStream_t s2;
  static cudaEvent_t e_fork1, e_join1, e_fork2, e_join2;
  if (!init_done) {
    cudaFuncSetAttribute(k_opair, cudaFuncAttributeMaxDynamicSharedMemorySize, OPAIR_SMEM);
    cudaFuncSetAttribute(k_bias7, cudaFuncAttributeMaxDynamicSharedMemorySize, BIAS_SMEM);
    cudaStreamCreateWithFlags(&s2, cudaStreamNonBlocking);
    cudaEventCreateWithFlags(&e_fork1, cudaEventDisableTiming);
    cudaEventCreateWithFlags(&e_join1, cudaEventDisableTiming);
    cudaEventCreateWithFlags(&e_fork2, cudaEventDisableTiming);
    cudaEventCreateWithFlags(&e_join2, cudaEventDisableTiming);
    init_done = true;
  }

  // Fork 1: bias (memory path) on s2, projections (compute path) on default.
  cudaEventRecord(e_fork1, 0);
  cudaStreamWaitEvent(s2, e_fork1, 0);
  k_bias7<<<1152, 128, BIAS_SMEM, s2>>>(z, w_b, b_b);
  cudaEventRecord(e_join1, s2);

  k_pack<<<1728, 256>>>(w_q, w_k, w_v, w_qp, w_kp, w_vp,
                        b_q, b_k, b_v, b_qp, b_kp, b_vp, hw);
  k_gemm1<<<dim3(12, 18), 256>>>(s);
  k_proj<<<N_, 128>>>(rot, trans);
  cudaStreamWaitEvent(0, e_join1, 0);

  k_logits<<<dim3(48, 12), 256>>>(mask);

  // Fork 2: k_opair on s2 concurrent with k_out on default.
  cudaEventRecord(e_fork2, 0);
  cudaStreamWaitEvent(s2, e_fork2, 0);
  k_opair<<<N_, 256, OPAIR_SMEM, s2>>>(z);
  cudaEventRecord(e_join2, s2);

  k_out<<<dim3(24, 12), 160>>>(rot, trans);
  cudaStreamWaitEvent(0, e_join2, 0);

  k_gemm2<<<dim3(12, 6, 3), 256>>>(w_o);
  k_add<<<1152, 256>>>(b_o, out);
}

// round 12
// speedup vs baseline: 1.0208x; 1.0208x over previous
#include <cuda_runtime.h>
#include <math.h>

#define N_ 768
#define CS 384
#define CZ 128
#define NH 12
#define LINW 1152
#define CATW 2112
#define INF_ 100000.0f
#define NK_ ((size_t)N_ * N_)   // 589824

// ---------------- device scratch ----------------
__device__ float g_wpack[CS * LINW];
__device__ float g_bpack[LINW];
__device__ float g_pw[NH];
__device__ float g_lin[N_ * LINW];
__device__ float g_qops[NH * N_ * 32];
__device__ float g_kops[NH * N_ * 32];
__device__ float g_vops[NH * N_ * 40];
__device__ float g_L[NH * NK_];
__device__ float g_cat[N_ * CATW];
__device__ float g_part[3][N_ * CS];

// ---------------- f32x2 helpers ----------------
typedef unsigned long long u64;
__device__ __forceinline__ u64 pk2(float a, float b) {
  u64 r;
  asm("mov.b64 %0, {%1,%2};" : "=l"(r) : "f"(a), "f"(b));
  return r;
}
__device__ __forceinline__ void upk2(u64 v, float& a, float& b) {
  asm("mov.b64 {%0,%1}, %2;" : "=f"(a), "=f"(b) : "l"(v));
}
__device__ __forceinline__ void fma2(u64& d, u64 a, u64 b) {
  asm("fma.rn.f32x2 %0, %1, %2, %0;" : "+l"(d) : "l"(a), "l"(b));
}

// ---------------- pack weights ----------------
__global__ void k_pack(const float* wq, const float* wk, const float* wv,
                       const float* wqp, const float* wkp, const float* wvp,
                       const float* bq, const float* bk, const float* bv,
                       const float* bqp, const float* bkp, const float* bvp,
                       const float* hw) {
  int idx = blockIdx.x * 256 + threadIdx.x;
  if (idx < CS * LINW) {
    int i = idx / LINW, j = idx - i * LINW;
    float v;
    if (j < 192)       v = wq[i * 192 + j];
    else if (j < 384)  v = wk[i * 192 + j - 192];
    else if (j < 576)  v = wv[i * 192 + j - 384];
    else if (j < 720)  v = wqp[i * 144 + j - 576];
    else if (j < 864)  v = wkp[i * 144 + j - 720];
    else               v = wvp[i * 288 + j - 864];
    g_wpack[idx] = v;
  }
  if (idx < LINW) {
    int j = idx;
    float v;
    if (j < 192)       v = bq[j];
    else if (j < 384)  v = bk[j - 192];
    else if (j < 576)  v = bv[j - 384];
    else if (j < 720)  v = bqp[j - 576];
    else if (j < 864)  v = bkp[j - 720];
    else               v = bvp[j - 864];
    g_bpack[j] = v;
  }
  if (idx < NH) {
    float h = hw[idx];
    g_pw[idx] = 0.23570226039551584f * (fmaxf(h, 0.f) + log1pf(expf(-fabsf(h))));
  }
}

// ---------------- GEMM 1: g_lin = s @ wpack (768x1152, K=384), pipelined ----------------
__global__ __launch_bounds__(256) void k_gemm1(const float* __restrict__ A) {
  __shared__ float aT[16][68];
  __shared__ float bT[16][68];
  int m0 = blockIdx.x * 64, n0 = blockIdx.y * 64;
  int t = threadIdx.x;
  int mi = (t & 15) * 4, ni = (t >> 4) * 4;
  u64 c2[4][2] = {};
  float a_pf[4], b_pf[4];
#pragma unroll
  for (int j = 0; j < 4; ++j) {
    int e = t + j * 256;
    a_pf[j] = A[(m0 + (e >> 4)) * CS + (e & 15)];
    b_pf[j] = g_wpack[(e >> 6) * LINW + n0 + (e & 63)];
  }
  for (int kt = 0; kt < 24; ++kt) {
    __syncthreads();
#pragma unroll
    for (int j = 0; j < 4; ++j) {
      int e = t + j * 256;
      aT[e & 15][e >> 4] = a_pf[j];
      bT[e >> 6][e & 63] = b_pf[j];
    }
    if (kt + 1 < 24) {
      int k0 = (kt + 1) * 16;
#pragma unroll
      for (int j = 0; j < 4; ++j) {
        int e = t + j * 256;
        a_pf[j] = A[(m0 + (e >> 4)) * CS + k0 + (e & 15)];
        b_pf[j] = g_wpack[(k0 + (e >> 6)) * LINW + n0 + (e & 63)];
      }
    }
    __syncthreads();
#pragma unroll
    for (int kk = 0; kk < 16; ++kk) {
      float4 a = *(const float4*)&aT[kk][mi];
      float4 b = *(const float4*)&bT[kk][ni];
      u64 b0 = pk2(b.x, b.y), b1 = pk2(b.z, b.w);
      u64 a0 = pk2(a.x, a.x), a1 = pk2(a.y, a.y), a2 = pk2(a.z, a.z), a3 = pk2(a.w, a.w);
      fma2(c2[0][0], a0, b0); fma2(c2[0][1], a0, b1);
      fma2(c2[1][0], a1, b0); fma2(c2[1][1], a1, b1);
      fma2(c2[2][0], a2, b0); fma2(c2[2][1], a2, b1);
      fma2(c2[3][0], a3, b0); fma2(c2[3][1], a3, b1);
    }
  }
#pragma unroll
  for (int r = 0; r < 4; ++r)
#pragma unroll
    for (int j = 0; j < 2; ++j) {
      float lo, hi;
      upk2(c2[r][j], lo, hi);
      g_lin[(m0 + mi + r) * LINW + n0 + ni + 2 * j] = lo;
      g_lin[(m0 + mi + r) * LINW + n0 + ni + 2 * j + 1] = hi;
    }
}

// ---------------- GEMM 2: part[z] = cat @ w_o (768x384, K=2112 split 3), pipelined ----------------
__global__ __launch_bounds__(256) void k_gemm2(const float* __restrict__ B) {
  __shared__ float aT[16][68];
  __shared__ float bT[16][68];
  int m0 = blockIdx.x * 64, n0 = blockIdx.y * 64;
  int t = threadIdx.x;
  int mi = (t & 15) * 4, ni = (t >> 4) * 4;
  u64 c2[4][2] = {};
  int kbase = blockIdx.z * 44 * 16;
  float a_pf[4], b_pf[4];
#pragma unroll
  for (int j = 0; j < 4; ++j) {
    int e = t + j * 256;
    a_pf[j] = g_cat[(m0 + (e >> 4)) * CATW + kbase + (e & 15)];
    b_pf[j] = B[(kbase + (e >> 6)) * CS + n0 + (e & 63)];
  }
  for (int kt = 0; kt < 44; ++kt) {
    __syncthreads();
#pragma unroll
    for (int j = 0; j < 4; ++j) {
      int e = t + j * 256;
      aT[e & 15][e >> 4] = a_pf[j];
      bT[e >> 6][e & 63] = b_pf[j];
    }
    if (kt + 1 < 44) {
      int k0 = kbase + (kt + 1) * 16;
#pragma unroll
      for (int j = 0; j < 4; ++j) {
        int e = t + j * 256;
        a_pf[j] = g_cat[(m0 + (e >> 4)) * CATW + k0 + (e & 15)];
        b_pf[j] = B[(k0 + (e >> 6)) * CS + n0 + (e & 63)];
      }
    }
    __syncthreads();
#pragma unroll
    for (int kk = 0; kk < 16; ++kk) {
      float4 a = *(const float4*)&aT[kk][mi];
      float4 b = *(const float4*)&bT[kk][ni];
      u64 b0 = pk2(b.x, b.y), b1 = pk2(b.z, b.w);
      u64 a0 = pk2(a.x, a.x), a1 = pk2(a.y, a.y), a2 = pk2(a.z, a.z), a3 = pk2(a.w, a.w);
      fma2(c2[0][0], a0, b0); fma2(c2[0][1], a0, b1);
      fma2(c2[1][0], a1, b0); fma2(c2[1][1], a1, b1);
      fma2(c2[2][0], a2, b0); fma2(c2[2][1], a2, b1);
      fma2(c2[3][0], a3, b0); fma2(c2[3][1], a3, b1);
    }
  }
  float* outp = &g_part[blockIdx.z][0];
#pragma unroll
  for (int r = 0; r < 4; ++r)
#pragma unroll
    for (int j = 0; j < 2; ++j) {
      float lo, hi;
      upk2(c2[r][j], lo, hi);
      outp[(m0 + mi + r) * CS + n0 + ni + 2 * j] = lo;
      outp[(m0 + mi + r) * CS + n0 + ni + 2 * j + 1] = hi;
    }
}

// ---------------- projection epilogue per residue ----------------
__global__ __launch_bounds__(128) void k_proj(const float* __restrict__ rot,
                                              const float* __restrict__ trans) {
  __shared__ float s2[24];
  int q = blockIdx.x, t = threadIdx.x;
  const float* lin = g_lin + q * LINW;
  if (t < 24) s2[t] = 0.f;
  __syncthreads();
  float R[9], tr[3];
#pragma unroll
  for (int j = 0; j < 9; ++j) R[j] = __ldg(rot + q * 9 + j);
#pragma unroll
  for (int j = 0; j < 3; ++j) tr[j] = __ldg(trans + q * 3 + j);
  for (int i = t; i < 192; i += 128) {
    int h = i >> 4, c = i & 15;
    g_qops[(h * N_ + q) * 32 + c] = (lin[i] + g_bpack[i]) * 0.25f;
    g_kops[(h * N_ + q) * 32 + c] = lin[192 + i] + g_bpack[192 + i];
    g_vops[(h * N_ + q) * 40 + c] = lin[384 + i] + g_bpack[384 + i];
  }
  if (t < 96) {
    int which = t / 48;
    int i = t % 48;
    int h = i >> 2, p = i & 3;
    int base = 576 + which * 144 + h * 12;
    float lx = lin[base + p] + g_bpack[base + p];
    float ly = lin[base + 4 + p] + g_bpack[base + 4 + p];
    float lz = lin[base + 8 + p] + g_bpack[base + 8 + p];
    float gx = R[0] * lx + R[1] * ly + R[2] * lz + tr[0];
    float gy = R[3] * lx + R[4] * ly + R[5] * lz + tr[1];
    float gz = R[6] * lx + R[7] * ly + R[8] * lz + tr[2];
    float n2 = gx * gx + gy * gy + gz * gz;
    int o = (h * N_ + q) * 32 + 16 + p * 3;
    if (which == 0) {
      g_qops[o] = gx; g_qops[o + 1] = gy; g_qops[o + 2] = gz;
      atomicAdd(&s2[h], n2);
    } else {
      g_kops[o] = gx; g_kops[o + 1] = gy; g_kops[o + 2] = gz;
      atomicAdd(&s2[12 + h], n2);
    }
  }
  if (t < 96) {
    int h = t >> 3, p = t & 7;
    int base = 864 + h * 24;
    float lx = lin[base + p] + g_bpack[base + p];
    float ly = lin[base + 8 + p] + g_bpack[base + 8 + p];
    float lz = lin[base + 16 + p] + g_bpack[base + 16 + p];
    float gx = R[0] * lx + R[1] * ly + R[2] * lz + tr[0];
    float gy = R[3] * lx + R[4] * ly + R[5] * lz + tr[1];
    float gz = R[6] * lx + R[7] * ly + R[8] * lz + tr[2];
    int o = (h * N_ + q) * 40 + 16 + p * 3;
    g_vops[o] = gx; g_vops[o + 1] = gy; g_vops[o + 2] = gz;
  }
  __syncthreads();
  if (t < 12) {
    g_qops[(t * N_ + q) * 32 + 28] = s2[t];
    g_kops[(t * N_ + q) * 32 + 28] = s2[12 + t];
  }
}

// ---------------- pair bias: k_bias8 — bias7 structure, 8-col chunks ----------------
// 512 rows/block, 128 threads, 4 rows/thread via f32x2 row-pair lanes.
// 16 chunks of 8 cols => smem 45KB => 2 blocks/SM (double bias7's concurrency).
__global__ __launch_bounds__(128) void k_bias8(const float* __restrict__ z,
                                               const float* __restrict__ wb,
                                               const float* __restrict__ bb) {
  extern __shared__ u64 sm8[];
  u64* zb0 = sm8;                 // [8][257]
  u64* zb1 = sm8 + 8 * 257;       // [8][257]
  u64* w2 = sm8 + 2 * 8 * 257;    // [128][12], each = pk2(w,w)
  int t = threadIdx.x;
  for (int idx = t; idx < 1536; idx += 128) {
    int c = idx / 12, h = idx - c * 12;
    float w = __ldg(wb + c * 12 + h);
    w2[idx] = pk2(w, w);
  }
  size_t R0 = (size_t)blockIdx.x * 512;
  int rp0 = t >> 1, j0 = t & 1;   // staging: 4 float4 pairs per thread

  float4 vA[4], vB[4];
  // load chunk 0 (cols 0..7)
#pragma unroll
  for (int i = 0; i < 4; ++i) {
    int idx = t + i * 128;
    int rp = idx >> 1, j = idx & 1;
    const float* pA = z + (R0 + rp) * CZ + 4 * j;
    vA[i] = *(const float4*)pA;
    vB[i] = *(const float4*)(pA + 256 * CZ);
  }
  // store chunk 0
#pragma unroll
  for (int i = 0; i < 4; ++i) {
    int idx = t + i * 128;
    int rp = idx >> 1, j = idx & 1;
    u64* d = zb0 + 4 * j * 257 + rp;
    d[0] = pk2(vA[i].x, vB[i].x);
    d[257] = pk2(vA[i].y, vB[i].y);
    d[514] = pk2(vA[i].z, vB[i].z);
    d[771] = pk2(vA[i].w, vB[i].w);
  }
  __syncthreads();

  u64 acc0[12] = {}, acc1[12] = {};
  for (int ch = 0; ch < 16; ++ch) {
    u64* cur = (ch & 1) ? zb1 : zb0;
    u64* nxt = (ch & 1) ? zb0 : zb1;
    if (ch < 15) {
      // prefetch next 8-col chunk before compute
#pragma unroll
      for (int i = 0; i < 4; ++i) {
        int idx = t + i * 128;
        int rp = idx >> 1, j = idx & 1;
        const float* pA = z + (R0 + rp) * CZ + (ch + 1) * 8 + 4 * j;
        vA[i] = *(const float4*)pA;
        vB[i] = *(const float4*)(pA + 256 * CZ);
      }
    }
    const u64* w2c = w2 + ch * 8 * 12;
#pragma unroll
    for (int cl = 0; cl < 8; ++cl) {
      u64 z0 = cur[cl * 257 + t];
      u64 z1 = cur[cl * 257 + t + 128];
      const u64* wr = w2c + cl * 12;
#pragma unroll
      for (int h = 0; h < 12; ++h) {
        u64 w = wr[h];
        fma2(acc0[h], z0, w);
        fma2(acc1[h], z1, w);
      }
    }
    if (ch < 15) {
#pragma unroll
      for (int i = 0; i < 4; ++i) {
        int idx = t + i * 128;
        int rp = idx >> 1, j = idx & 1;
        u64* d = nxt + 4 * j * 257 + rp;
        d[0] = pk2(vA[i].x, vB[i].x);
        d[257] = pk2(vA[i].y, vB[i].y);
        d[514] = pk2(vA[i].z, vB[i].z);
        d[771] = pk2(vA[i].w, vB[i].w);
      }
    }
    __syncthreads();
  }
  // acc0 lanes = rows (R0+t, R0+t+256); acc1 lanes = (R0+t+128, R0+t+384)
#pragma unroll
  for (int h = 0; h < 12; ++h) {
    float bbh = __ldg(bb + h);
    float a, b, c, d;
    upk2(acc0[h], a, b);
    upk2(acc1[h], c, d);
    float* Lp = g_L + (size_t)h * NK_ + R0;
    Lp[t] = a + bbh;
    Lp[t + 256] = b + bbh;
    Lp[t + 128] = c + bbh;
    Lp[t + 384] = d + bbh;
  }
}

// ---------------- logits + softmax (in place on g_L) ----------------
__global__ __launch_bounds__(256) void k_logits(const float* __restrict__ mask) {
  __shared__ float ks[256 * 36];
  int t = threadIdx.x;
  int h = blockIdx.y;
  int Q0 = blockIdx.x * 16;
  int ql = t >> 4, s = t & 15;
  int q = Q0 + ql;
  const float* qop = g_qops + ((size_t)h * N_ + q) * 32;
  const u64* qop8 = (const u64*)qop;
  u64 qh_u[8], qp_u[6];
#pragma unroll
  for (int i = 0; i < 8; ++i) qh_u[i] = qop8[i];
#pragma unroll
  for (int i = 0; i < 6; ++i) qp_u[i] = qop8[8 + i];
  float q2 = qop[28];
  float pw = g_pw[h];
  float cb = -0.5f * pw * q2;
  float mq = __ldg(mask + q);
  const float* Lrow = g_L + ((size_t)h * N_ + q) * N_;
  float lg[48];
#pragma unroll
  for (int ch = 0; ch < 3; ++ch) {
    int k0 = ch * 256;
    __syncthreads();
#pragma unroll
    for (int i = 0; i < 8; ++i) {
      int idx = t + i * 256;
      int row = idx >> 3, f4 = idx & 7;
      *(float4*)(ks + row * 36 + f4 * 4) =
          *(const float4*)(g_kops + ((size_t)h * N_ + k0 + row) * 32 + f4 * 4);
    }
    __syncthreads();
#pragma unroll
    for (int jj = 0; jj < 16; ++jj) {
      int kl = s + 16 * jj;
      const u64* kr8 = (const u64*)(ks + kl * 36);
      u64 d2 = 0, e2 = 0;
#pragma unroll
      for (int i = 0; i < 8; ++i) fma2(d2, kr8[i], qh_u[i]);
#pragma unroll
      for (int i = 0; i < 6; ++i) fma2(e2, kr8[8 + i], qp_u[i]);
      float dlo, dhi, elo, ehi;
      upk2(d2, dlo, dhi);
      upk2(e2, elo, ehi);
      float k2s = ks[kl * 36 + 28];
      int k = k0 + kl;
      lg[ch * 16 + jj] = Lrow[k] + dlo + dhi + pw * (elo + ehi - 0.5f * k2s) + cb
                         + INF_ * (mq * __ldg(mask + k) - 1.f);
    }
  }
  float mx = -3.0e38f;
#pragma unroll
  for (int i = 0; i < 48; ++i) mx = fmaxf(mx, lg[i]);
  mx = fmaxf(mx, __shfl_xor_sync(0xffffffffu, mx, 1));
  mx = fmaxf(mx, __shfl_xor_sync(0xffffffffu, mx, 2));
  mx = fmaxf(mx, __shfl_xor_sync(0xffffffffu, mx, 4));
  mx = fmaxf(mx, __shfl_xor_sync(0xffffffffu, mx, 8));
  float sum = 0.f;
#pragma unroll
  for (int i = 0; i < 48; ++i) {
    float w = __expf(0.57735026919f * (lg[i] - mx));
    lg[i] = w;
    sum += w;
  }
  sum += __shfl_xor_sync(0xffffffffu, sum, 1);
  sum += __shfl_xor_sync(0xffffffffu, sum, 2);
  sum += __shfl_xor_sync(0xffffffffu, sum, 4);
  sum += __shfl_xor_sync(0xffffffffu, sum, 8);
  float inv = 1.f / sum;
  float* Lw = g_L + ((size_t)h * N_ + q) * N_;
#pragma unroll
  for (int ch = 0; ch < 3; ++ch)
#pragma unroll
    for (int jj = 0; jj < 16; ++jj)
      Lw[ch * 256 + s + 16 * jj] = lg[ch * 16 + jj] * inv;
}

// ---------------- o + o_pt + norms ----------------
__global__ __launch_bounds__(160) void k_out(const float* __restrict__ rot,
                                             const float* __restrict__ trans) {
  __shared__ float as[32 * 132];
  __shared__ float vs[128 * 44];
  __shared__ float os[32 * 40];
  int t = threadIdx.x;
  int h = blockIdx.y;
  int Q0 = blockIdx.x * 32;
  int q = t / 5, s = t - q * 5;
  u64 acc2[4] = {};
  for (int ch = 0; ch < 6; ++ch) {
    int k0 = ch * 128;
    __syncthreads();
    for (int idx = t; idx < 1024; idx += 160) {
      int qq = idx >> 5, f4 = idx & 31;
      *(float4*)(as + qq * 132 + f4 * 4) =
          *(const float4*)(g_L + ((size_t)h * N_ + Q0 + qq) * N_ + k0 + f4 * 4);
    }
    for (int idx = t; idx < 1280; idx += 160) {
      int row = idx / 10, f4 = idx - row * 10;
      *(float4*)(vs + row * 44 + f4 * 4) =
          *(const float4*)(g_vops + ((size_t)h * N_ + k0 + row) * 40 + f4 * 4);
    }
    __syncthreads();
#pragma unroll 4
    for (int kl = 0; kl < 128; ++kl) {
      float a = as[q * 132 + kl];
      u64 au = pk2(a, a);
      const u64* vp = (const u64*)(vs + kl * 44 + 8 * s);
      fma2(acc2[0], vp[0], au);
      fma2(acc2[1], vp[1], au);
      fma2(acc2[2], vp[2], au);
      fma2(acc2[3], vp[3], au);
    }
  }
#pragma unroll
  for (int i = 0; i < 4; ++i) {
    float lo, hi;
    upk2(acc2[i], lo, hi);
    os[q * 40 + 8 * s + 2 * i] = lo;
    os[q * 40 + 8 * s + 2 * i + 1] = hi;
  }
  __syncthreads();
  for (int idx = t; idx < 512; idx += 160) {
    int qq = idx >> 4, c = idx & 15;
    g_cat[(size_t)(Q0 + qq) * CATW + h * 16 + c] = os[qq * 40 + c];
  }
  for (int idx = t; idx < 256; idx += 160) {
    int qq = idx >> 3, p = idx & 7;
    int gq = Q0 + qq;
    float ex = os[qq * 40 + 16 + 3 * p] - __ldg(trans + gq * 3 + 0);
    float ey = os[qq * 40 + 17 + 3 * p] - __ldg(trans + gq * 3 + 1);
    float ez = os[qq * 40 + 18 + 3 * p] - __ldg(trans + gq * 3 + 2);
    const float* R = rot + gq * 9;
    float lx = __ldg(R + 0) * ex + __ldg(R + 3) * ey + __ldg(R + 6) * ez;
    float ly = __ldg(R + 1) * ex + __ldg(R + 4) * ey + __ldg(R + 7) * ez;
    float lz = __ldg(R + 2) * ex + __ldg(R + 5) * ey + __ldg(R + 8) * ez;
    float* cp = g_cat + (size_t)gq * CATW + 192 + h * 8 + p;
    cp[0] = lx;
    cp[96] = ly;
    cp[192] = lz;
    cp[288] = sqrtf(lx * lx + ly * ly + lz * lz + 1e-8f);
  }
}

// ---------------- o_pair (round-8 version — do not touch) ----------------
__global__ __launch_bounds__(256) void k_opair(const float* __restrict__ z) {
  extern __shared__ float sm[];
  float* aT = sm;  // [768][20]
  int t = threadIdx.x;
  int q = blockIdx.x;
#pragma unroll
  for (int h = 0; h < 12; ++h)
    for (int kk = t; kk < N_; kk += 256)
      aT[kk * 20 + h] = g_L[((size_t)h * N_ + q) * N_ + kk];
  __syncthreads();
  int c2 = (t & 63) * 2, kg = t >> 6;
  const float* zq = z + (size_t)q * N_ * CZ;
  u64 acc[12] = {};
#pragma unroll 4
  for (int k = kg; k < N_; k += 4) {
    u64 zd = *(const u64*)(zq + (size_t)k * CZ + c2);
    const float* ar = aT + k * 20;
    float4 a0 = *(const float4*)ar;
    float4 a1 = *(const float4*)(ar + 4);
    float4 a2 = *(const float4*)(ar + 8);
    float av[12] = {a0.x, a0.y, a0.z, a0.w, a1.x, a1.y, a1.z, a1.w,
                    a2.x, a2.y, a2.z, a2.w};
#pragma unroll
    for (int h = 0; h < 12; ++h) fma2(acc[h], zd, pk2(av[h], av[h]));
  }
  __syncthreads();
  u64* buf = (u64*)sm;  // [256][12]
#pragma unroll
  for (int h = 0; h < 12; ++h) buf[t * 12 + h] = acc[h];
  __syncthreads();
  for (int idx = t; idx < 1536; idx += 256) {
    int h = idx >> 7, c = idx & 127;
    float sum = 0.f;
#pragma unroll
    for (int g = 0; g < 4; ++g) {
      float lo, hi;
      upk2(buf[(g * 64 + (c >> 1)) * 12 + h], lo, hi);
      sum += (c & 1) ? hi : lo;
    }
    g_cat[(size_t)q * CATW + 576 + h * 128 + c] = sum;
  }
}

// ---------------- final add ----------------
__global__ void k_add(const float* __restrict__ bo, float* __restrict__ out) {
  int i = blockIdx.x * 256 + threadIdx.x;
  if (i < N_ * CS) {
    int col = i % CS;
    out[i] = g_part[0][i] + g_part[1][i] + g_part[2][i] + __ldg(bo + col);
  }
}

extern "C" void kernel_launch(void* const* d_in, const int* in_sizes, int n_in,
                              void* d_out, int out_size) {
  const float* s     = (const float*)d_in[0];
  const float* z     = (const float*)d_in[1];
  const float* rot   = (const float*)d_in[2];
  const float* trans = (const float*)d_in[3];
  const float* mask  = (const float*)d_in[4];
  const float* w_q   = (const float*)d_in[5];
  const float* b_q   = (const float*)d_in[6];
  const float* w_k   = (const float*)d_in[7];
  const float* b_k   = (const float*)d_in[8];
  const float* w_v   = (const float*)d_in[9];
  const float* b_v   = (const float*)d_in[10];
  const float* w_qp  = (const float*)d_in[11];
  const float* b_qp  = (const float*)d_in[12];
  const float* w_kp  = (const float*)d_in[13];
  const float* b_kp  = (const float*)d_in[14];
  const float* w_vp  = (const float*)d_in[15];
  const float* b_vp  = (const float*)d_in[16];
  const float* w_b   = (const float*)d_in[17];
  const float* b_b   = (const float*)d_in[18];
  const float* hw    = (const float*)d_in[19];
  const float* w_o   = (const float*)d_in[20];
  const float* b_o   = (const float*)d_in[21];
  float* out = (float*)d_out;

  const int BIAS_SMEM = (2 * 8 * 257 + 1536) * 8;  // 45184 bytes

  static bool init_done = false;
  static cudaStream_t s2;
  static cudaEvent_t e_fork1, e_join1, e_fork2, e_join2;
  if (!init_done) {
    cudaFuncSetAttribute(k_opair, cudaFuncAttributeMaxDynamicSharedMemorySize, 65536);
    cudaFuncSetAttribute(k_bias8, cudaFuncAttributeMaxDynamicSharedMemorySize, BIAS_SMEM);
    cudaStreamCreateWithFlags(&s2, cudaStreamNonBlocking);
    cudaEventCreateWithFlags(&e_fork1, cudaEventDisableTiming);
    cudaEventCreateWithFlags(&e_join1, cudaEventDisableTiming);
    cudaEventCreateWithFlags(&e_fork2, cudaEventDisableTiming);
    cudaEventCreateWithFlags(&e_join2, cudaEventDisableTiming);
    init_done = true;
  }

  // Fork 1: bias (memory path) on s2, projections (compute path) on default.
  cudaEventRecord(e_fork1, 0);
  cudaStreamWaitEvent(s2, e_fork1, 0);
  k_bias8<<<1152, 128, BIAS_SMEM, s2>>>(z, w_b, b_b);
  cudaEventRecord(e_join1, s2);

  k_pack<<<1728, 256>>>(w_q, w_k, w_v, w_qp, w_kp, w_vp,
                        b_q, b_k, b_v, b_qp, b_kp, b_vp, hw);
  k_gemm1<<<dim3(12, 18), 256>>>(s);
  k_proj<<<N_, 128>>>(rot, trans);
  cudaStreamWaitEvent(0, e_join1, 0);

  k_logits<<<dim3(48, 12), 256>>>(mask);

  // Fork 2: k_opair on s2 concurrent with k_out on default.
  cudaEventRecord(e_fork2, 0);
  cudaStreamWaitEvent(s2, e_fork2, 0);
  k_opair<<<N_, 256, 768 * 20 * 4, s2>>>(z);
  cudaEventRecord(e_join2, s2);

  k_out<<<dim3(24, 12), 160>>>(rot, trans);
  cudaStreamWaitEvent(0, e_join2, 0);

  k_gemm2<<<dim3(12, 6, 3), 256>>>(w_o);
  k_add<<<1152, 256>>>(b_o, out);
}

// round 13
// speedup vs baseline: 1.0382x; 1.0170x over previous
#include <cuda_runtime.h>
#include <math.h>

#define N_ 768
#define CS 384
#define CZ 128
#define NH 12
#define LINW 1152
#define CATW 2112
#define INF_ 100000.0f
#define NK_ ((size_t)N_ * N_)   // 589824

// ---------------- device scratch ----------------
__device__ float g_wpack[CS * LINW];
__device__ float g_bpack[LINW];
__device__ float g_pw[NH];
__device__ float g_lin[N_ * LINW];
__device__ float g_qops[NH * N_ * 32];
__device__ float g_kops[NH * N_ * 32];
__device__ float g_vops[NH * N_ * 40];
__device__ float g_L[NH * NK_];
__device__ float g_cat[N_ * CATW];
__device__ float g_part[3][N_ * CS];

// ---------------- f32x2 helpers ----------------
typedef unsigned long long u64;
__device__ __forceinline__ u64 pk2(float a, float b) {
  u64 r;
  asm("mov.b64 %0, {%1,%2};" : "=l"(r) : "f"(a), "f"(b));
  return r;
}
__device__ __forceinline__ void upk2(u64 v, float& a, float& b) {
  asm("mov.b64 {%0,%1}, %2;" : "=f"(a), "=f"(b) : "l"(v));
}
__device__ __forceinline__ void fma2(u64& d, u64 a, u64 b) {
  asm("fma.rn.f32x2 %0, %1, %2, %0;" : "+l"(d) : "l"(a), "l"(b));
}

// ---------------- pack weights ----------------
__global__ void k_pack(const float* wq, const float* wk, const float* wv,
                       const float* wqp, const float* wkp, const float* wvp,
                       const float* bq, const float* bk, const float* bv,
                       const float* bqp, const float* bkp, const float* bvp,
                       const float* hw) {
  int idx = blockIdx.x * 256 + threadIdx.x;
  if (idx < CS * LINW) {
    int i = idx / LINW, j = idx - i * LINW;
    float v;
    if (j < 192)       v = wq[i * 192 + j];
    else if (j < 384)  v = wk[i * 192 + j - 192];
    else if (j < 576)  v = wv[i * 192 + j - 384];
    else if (j < 720)  v = wqp[i * 144 + j - 576];
    else if (j < 864)  v = wkp[i * 144 + j - 720];
    else               v = wvp[i * 288 + j - 864];
    g_wpack[idx] = v;
  }
  if (idx < LINW) {
    int j = idx;
    float v;
    if (j < 192)       v = bq[j];
    else if (j < 384)  v = bk[j - 192];
    else if (j < 576)  v = bv[j - 384];
    else if (j < 720)  v = bqp[j - 576];
    else if (j < 864)  v = bkp[j - 720];
    else               v = bvp[j - 864];
    g_bpack[j] = v;
  }
  if (idx < NH) {
    float h = hw[idx];
    g_pw[idx] = 0.23570226039551584f * (fmaxf(h, 0.f) + log1pf(expf(-fabsf(h))));
  }
}

// ---------------- GEMM 1: g_lin = s @ wpack (768x1152, K=384), pipelined ----------------
__global__ __launch_bounds__(256) void k_gemm1(const float* __restrict__ A) {
  __shared__ float aT[16][68];
  __shared__ float bT[16][68];
  int m0 = blockIdx.x * 64, n0 = blockIdx.y * 64;
  int t = threadIdx.x;
  int mi = (t & 15) * 4, ni = (t >> 4) * 4;
  u64 c2[4][2] = {};
  float a_pf[4], b_pf[4];
#pragma unroll
  for (int j = 0; j < 4; ++j) {
    int e = t + j * 256;
    a_pf[j] = A[(m0 + (e >> 4)) * CS + (e & 15)];
    b_pf[j] = g_wpack[(e >> 6) * LINW + n0 + (e & 63)];
  }
  for (int kt = 0; kt < 24; ++kt) {
    __syncthreads();
#pragma unroll
    for (int j = 0; j < 4; ++j) {
      int e = t + j * 256;
      aT[e & 15][e >> 4] = a_pf[j];
      bT[e >> 6][e & 63] = b_pf[j];
    }
    if (kt + 1 < 24) {
      int k0 = (kt + 1) * 16;
#pragma unroll
      for (int j = 0; j < 4; ++j) {
        int e = t + j * 256;
        a_pf[j] = A[(m0 + (e >> 4)) * CS + k0 + (e & 15)];
        b_pf[j] = g_wpack[(k0 + (e >> 6)) * LINW + n0 + (e & 63)];
      }
    }
    __syncthreads();
#pragma unroll
    for (int kk = 0; kk < 16; ++kk) {
      float4 a = *(const float4*)&aT[kk][mi];
      float4 b = *(const float4*)&bT[kk][ni];
      u64 b0 = pk2(b.x, b.y), b1 = pk2(b.z, b.w);
      u64 a0 = pk2(a.x, a.x), a1 = pk2(a.y, a.y), a2 = pk2(a.z, a.z), a3 = pk2(a.w, a.w);
      fma2(c2[0][0], a0, b0); fma2(c2[0][1], a0, b1);
      fma2(c2[1][0], a1, b0); fma2(c2[1][1], a1, b1);
      fma2(c2[2][0], a2, b0); fma2(c2[2][1], a2, b1);
      fma2(c2[3][0], a3, b0); fma2(c2[3][1], a3, b1);
    }
  }
#pragma unroll
  for (int r = 0; r < 4; ++r)
#pragma unroll
    for (int j = 0; j < 2; ++j) {
      float lo, hi;
      upk2(c2[r][j], lo, hi);
      g_lin[(m0 + mi + r) * LINW + n0 + ni + 2 * j] = lo;
      g_lin[(m0 + mi + r) * LINW + n0 + ni + 2 * j + 1] = hi;
    }
}

// ---------------- GEMM 2: part[part] += cat[:, 16*kstart : 16*(kstart+ntiles)] @ w_o ----------------
__global__ __launch_bounds__(256) void k_gemm2(const float* __restrict__ B,
                                               int kstart, int ntiles, int part) {
  __shared__ float aT[16][68];
  __shared__ float bT[16][68];
  int m0 = blockIdx.x * 64, n0 = blockIdx.y * 64;
  int t = threadIdx.x;
  int mi = (t & 15) * 4, ni = (t >> 4) * 4;
  u64 c2[4][2] = {};
  int kbase = kstart * 16;
  float a_pf[4], b_pf[4];
#pragma unroll
  for (int j = 0; j < 4; ++j) {
    int e = t + j * 256;
    a_pf[j] = g_cat[(m0 + (e >> 4)) * CATW + kbase + (e & 15)];
    b_pf[j] = B[(kbase + (e >> 6)) * CS + n0 + (e & 63)];
  }
  for (int kt = 0; kt < ntiles; ++kt) {
    __syncthreads();
#pragma unroll
    for (int j = 0; j < 4; ++j) {
      int e = t + j * 256;
      aT[e & 15][e >> 4] = a_pf[j];
      bT[e >> 6][e & 63] = b_pf[j];
    }
    if (kt + 1 < ntiles) {
      int k0 = kbase + (kt + 1) * 16;
#pragma unroll
      for (int j = 0; j < 4; ++j) {
        int e = t + j * 256;
        a_pf[j] = g_cat[(m0 + (e >> 4)) * CATW + k0 + (e & 15)];
        b_pf[j] = B[(k0 + (e >> 6)) * CS + n0 + (e & 63)];
      }
    }
    __syncthreads();
#pragma unroll
    for (int kk = 0; kk < 16; ++kk) {
      float4 a = *(const float4*)&aT[kk][mi];
      float4 b = *(const float4*)&bT[kk][ni];
      u64 b0 = pk2(b.x, b.y), b1 = pk2(b.z, b.w);
      u64 a0 = pk2(a.x, a.x), a1 = pk2(a.y, a.y), a2 = pk2(a.z, a.z), a3 = pk2(a.w, a.w);
      fma2(c2[0][0], a0, b0); fma2(c2[0][1], a0, b1);
      fma2(c2[1][0], a1, b0); fma2(c2[1][1], a1, b1);
      fma2(c2[2][0], a2, b0); fma2(c2[2][1], a2, b1);
      fma2(c2[3][0], a3, b0); fma2(c2[3][1], a3, b1);
    }
  }
  float* outp = &g_part[part][0];
#pragma unroll
  for (int r = 0; r < 4; ++r)
#pragma unroll
    for (int j = 0; j < 2; ++j) {
      float lo, hi;
      upk2(c2[r][j], lo, hi);
      outp[(m0 + mi + r) * CS + n0 + ni + 2 * j] = lo;
      outp[(m0 + mi + r) * CS + n0 + ni + 2 * j + 1] = hi;
    }
}

// ---------------- projection epilogue per residue ----------------
__global__ __launch_bounds__(128) void k_proj(const float* __restrict__ rot,
                                              const float* __restrict__ trans) {
  __shared__ float s2[24];
  int q = blockIdx.x, t = threadIdx.x;
  const float* lin = g_lin + q * LINW;
  if (t < 24) s2[t] = 0.f;
  __syncthreads();
  float R[9], tr[3];
#pragma unroll
  for (int j = 0; j < 9; ++j) R[j] = __ldg(rot + q * 9 + j);
#pragma unroll
  for (int j = 0; j < 3; ++j) tr[j] = __ldg(trans + q * 3 + j);
  for (int i = t; i < 192; i += 128) {
    int h = i >> 4, c = i & 15;
    g_qops[(h * N_ + q) * 32 + c] = (lin[i] + g_bpack[i]) * 0.25f;
    g_kops[(h * N_ + q) * 32 + c] = lin[192 + i] + g_bpack[192 + i];
    g_vops[(h * N_ + q) * 40 + c] = lin[384 + i] + g_bpack[384 + i];
  }
  if (t < 96) {
    int which = t / 48;
    int i = t % 48;
    int h = i >> 2, p = i & 3;
    int base = 576 + which * 144 + h * 12;
    float lx = lin[base + p] + g_bpack[base + p];
    float ly = lin[base + 4 + p] + g_bpack[base + 4 + p];
    float lz = lin[base + 8 + p] + g_bpack[base + 8 + p];
    float gx = R[0] * lx + R[1] * ly + R[2] * lz + tr[0];
    float gy = R[3] * lx + R[4] * ly + R[5] * lz + tr[1];
    float gz = R[6] * lx + R[7] * ly + R[8] * lz + tr[2];
    float n2 = gx * gx + gy * gy + gz * gz;
    int o = (h * N_ + q) * 32 + 16 + p * 3;
    if (which == 0) {
      g_qops[o] = gx; g_qops[o + 1] = gy; g_qops[o + 2] = gz;
      atomicAdd(&s2[h], n2);
    } else {
      g_kops[o] = gx; g_kops[o + 1] = gy; g_kops[o + 2] = gz;
      atomicAdd(&s2[12 + h], n2);
    }
  }
  if (t < 96) {
    int h = t >> 3, p = t & 7;
    int base = 864 + h * 24;
    float lx = lin[base + p] + g_bpack[base + p];
    float ly = lin[base + 8 + p] + g_bpack[base + 8 + p];
    float lz = lin[base + 16 + p] + g_bpack[base + 16 + p];
    float gx = R[0] * lx + R[1] * ly + R[2] * lz + tr[0];
    float gy = R[3] * lx + R[4] * ly + R[5] * lz + tr[1];
    float gz = R[6] * lx + R[7] * ly + R[8] * lz + tr[2];
    int o = (h * N_ + q) * 40 + 16 + p * 3;
    g_vops[o] = gx; g_vops[o + 1] = gy; g_vops[o + 2] = gz;
  }
  __syncthreads();
  if (t < 12) {
    g_qops[(t * N_ + q) * 32 + 28] = s2[t];
    g_kops[(t * N_ + q) * 32 + 28] = s2[12 + t];
  }
}

// ---------------- pair bias (k_bias7 + block offset for half-splits) ----------------
__global__ __launch_bounds__(128) void k_bias7(const float* __restrict__ z,
                                               const float* __restrict__ wb,
                                               const float* __restrict__ bb,
                                               int blk0) {
  extern __shared__ u64 sm7[];
  u64* zb0 = sm7;
  u64* zb1 = sm7 + 16 * 257;
  u64* w2 = sm7 + 2 * 16 * 257;
  int t = threadIdx.x;
  for (int idx = t; idx < 1536; idx += 128) {
    int c = idx / 12, h = idx - c * 12;
    float w = __ldg(wb + c * 12 + h);
    w2[idx] = pk2(w, w);
  }
  size_t R0 = (size_t)(blockIdx.x + blk0) * 512;

  float4 vA[8], vB[8];
#pragma unroll
  for (int i = 0; i < 8; ++i) {
    int idx = t + i * 128;
    int rp = idx >> 2, j = idx & 3;
    const float* pA = z + (R0 + rp) * CZ + 4 * j;
    vA[i] = *(const float4*)pA;
    vB[i] = *(const float4*)(pA + 256 * CZ);
  }
#pragma unroll
  for (int i = 0; i < 8; ++i) {
    int idx = t + i * 128;
    int rp = idx >> 2, j = idx & 3;
    u64* d = zb0 + 4 * j * 257 + rp;
    d[0] = pk2(vA[i].x, vB[i].x);
    d[257] = pk2(vA[i].y, vB[i].y);
    d[514] = pk2(vA[i].z, vB[i].z);
    d[771] = pk2(vA[i].w, vB[i].w);
  }
  __syncthreads();

  u64 acc0[12] = {}, acc1[12] = {};
  for (int ch = 0; ch < 8; ++ch) {
    u64* cur = (ch & 1) ? zb1 : zb0;
    u64* nxt = (ch & 1) ? zb0 : zb1;
    if (ch < 7) {
#pragma unroll
      for (int i = 0; i < 8; ++i) {
        int idx = t + i * 128;
        int rp = idx >> 2, j = idx & 3;
        const float* pA = z + (R0 + rp) * CZ + (ch + 1) * 16 + 4 * j;
        vA[i] = *(const float4*)pA;
        vB[i] = *(const float4*)(pA + 256 * CZ);
      }
    }
    const u64* w2c = w2 + ch * 16 * 12;
#pragma unroll
    for (int cl = 0; cl < 16; ++cl) {
      u64 z0 = cur[cl * 257 + t];
      u64 z1 = cur[cl * 257 + t + 128];
      const u64* wr = w2c + cl * 12;
#pragma unroll
      for (int h = 0; h < 12; ++h) {
        u64 w = wr[h];
        fma2(acc0[h], z0, w);
        fma2(acc1[h], z1, w);
      }
    }
    if (ch < 7) {
#pragma unroll
      for (int i = 0; i < 8; ++i) {
        int idx = t + i * 128;
        int rp = idx >> 2, j = idx & 3;
        u64* d = nxt + 4 * j * 257 + rp;
        d[0] = pk2(vA[i].x, vB[i].x);
        d[257] = pk2(vA[i].y, vB[i].y);
        d[514] = pk2(vA[i].z, vB[i].z);
        d[771] = pk2(vA[i].w, vB[i].w);
      }
    }
    __syncthreads();
  }
#pragma unroll
  for (int h = 0; h < 12; ++h) {
    float bbh = __ldg(bb + h);
    float a, b, c, d;
    upk2(acc0[h], a, b);
    upk2(acc1[h], c, d);
    float* Lp = g_L + (size_t)h * NK_ + R0;
    Lp[t] = a + bbh;
    Lp[t + 256] = b + bbh;
    Lp[t + 128] = c + bbh;
    Lp[t + 384] = d + bbh;
  }
}

// ---------------- logits + softmax (in place on g_L; qblk0 for half-splits) ----------------
__global__ __launch_bounds__(256) void k_logits(const float* __restrict__ mask, int qblk0) {
  __shared__ float ks[256 * 36];
  int t = threadIdx.x;
  int h = blockIdx.y;
  int Q0 = (blockIdx.x + qblk0) * 16;
  int ql = t >> 4, s = t & 15;
  int q = Q0 + ql;
  const float* qop = g_qops + ((size_t)h * N_ + q) * 32;
  const u64* qop8 = (const u64*)qop;
  u64 qh_u[8], qp_u[6];
#pragma unroll
  for (int i = 0; i < 8; ++i) qh_u[i] = qop8[i];
#pragma unroll
  for (int i = 0; i < 6; ++i) qp_u[i] = qop8[8 + i];
  float q2 = qop[28];
  float pw = g_pw[h];
  float cb = -0.5f * pw * q2;
  float mq = __ldg(mask + q);
  const float* Lrow = g_L + ((size_t)h * N_ + q) * N_;
  float lg[48];
#pragma unroll
  for (int ch = 0; ch < 3; ++ch) {
    int k0 = ch * 256;
    __syncthreads();
#pragma unroll
    for (int i = 0; i < 8; ++i) {
      int idx = t + i * 256;
      int row = idx >> 3, f4 = idx & 7;
      *(float4*)(ks + row * 36 + f4 * 4) =
          *(const float4*)(g_kops + ((size_t)h * N_ + k0 + row) * 32 + f4 * 4);
    }
    __syncthreads();
#pragma unroll
    for (int jj = 0; jj < 16; ++jj) {
      int kl = s + 16 * jj;
      const u64* kr8 = (const u64*)(ks + kl * 36);
      u64 d2 = 0, e2 = 0;
#pragma unroll
      for (int i = 0; i < 8; ++i) fma2(d2, kr8[i], qh_u[i]);
#pragma unroll
      for (int i = 0; i < 6; ++i) fma2(e2, kr8[8 + i], qp_u[i]);
      float dlo, dhi, elo, ehi;
      upk2(d2, dlo, dhi);
      upk2(e2, elo, ehi);
      float k2s = ks[kl * 36 + 28];
      int k = k0 + kl;
      lg[ch * 16 + jj] = Lrow[k] + dlo + dhi + pw * (elo + ehi - 0.5f * k2s) + cb
                         + INF_ * (mq * __ldg(mask + k) - 1.f);
    }
  }
  float mx = -3.0e38f;
#pragma unroll
  for (int i = 0; i < 48; ++i) mx = fmaxf(mx, lg[i]);
  mx = fmaxf(mx, __shfl_xor_sync(0xffffffffu, mx, 1));
  mx = fmaxf(mx, __shfl_xor_sync(0xffffffffu, mx, 2));
  mx = fmaxf(mx, __shfl_xor_sync(0xffffffffu, mx, 4));
  mx = fmaxf(mx, __shfl_xor_sync(0xffffffffu, mx, 8));
  float sum = 0.f;
#pragma unroll
  for (int i = 0; i < 48; ++i) {
    float w = __expf(0.57735026919f * (lg[i] - mx));
    lg[i] = w;
    sum += w;
  }
  sum += __shfl_xor_sync(0xffffffffu, sum, 1);
  sum += __shfl_xor_sync(0xffffffffu, sum, 2);
  sum += __shfl_xor_sync(0xffffffffu, sum, 4);
  sum += __shfl_xor_sync(0xffffffffu, sum, 8);
  float inv = 1.f / sum;
  float* Lw = g_L + ((size_t)h * N_ + q) * N_;
#pragma unroll
  for (int ch = 0; ch < 3; ++ch)
#pragma unroll
    for (int jj = 0; jj < 16; ++jj)
      Lw[ch * 256 + s + 16 * jj] = lg[ch * 16 + jj] * inv;
}

// ---------------- o + o_pt + norms ----------------
__global__ __launch_bounds__(160) void k_out(const float* __restrict__ rot,
                                             const float* __restrict__ trans) {
  __shared__ float as[32 * 132];
  __shared__ float vs[128 * 44];
  __shared__ float os[32 * 40];
  int t = threadIdx.x;
  int h = blockIdx.y;
  int Q0 = blockIdx.x * 32;
  int q = t / 5, s = t - q * 5;
  u64 acc2[4] = {};
  for (int ch = 0; ch < 6; ++ch) {
    int k0 = ch * 128;
    __syncthreads();
    for (int idx = t; idx < 1024; idx += 160) {
      int qq = idx >> 5, f4 = idx & 31;
      *(float4*)(as + qq * 132 + f4 * 4) =
          *(const float4*)(g_L + ((size_t)h * N_ + Q0 + qq) * N_ + k0 + f4 * 4);
    }
    for (int idx = t; idx < 1280; idx += 160) {
      int row = idx / 10, f4 = idx - row * 10;
      *(float4*)(vs + row * 44 + f4 * 4) =
          *(const float4*)(g_vops + ((size_t)h * N_ + k0 + row) * 40 + f4 * 4);
    }
    __syncthreads();
#pragma unroll 4
    for (int kl = 0; kl < 128; ++kl) {
      float a = as[q * 132 + kl];
      u64 au = pk2(a, a);
      const u64* vp = (const u64*)(vs + kl * 44 + 8 * s);
      fma2(acc2[0], vp[0], au);
      fma2(acc2[1], vp[1], au);
      fma2(acc2[2], vp[2], au);
      fma2(acc2[3], vp[3], au);
    }
  }
#pragma unroll
  for (int i = 0; i < 4; ++i) {
    float lo, hi;
    upk2(acc2[i], lo, hi);
    os[q * 40 + 8 * s + 2 * i] = lo;
    os[q * 40 + 8 * s + 2 * i + 1] = hi;
  }
  __syncthreads();
  for (int idx = t; idx < 512; idx += 160) {
    int qq = idx >> 4, c = idx & 15;
    g_cat[(size_t)(Q0 + qq) * CATW + h * 16 + c] = os[qq * 40 + c];
  }
  for (int idx = t; idx < 256; idx += 160) {
    int qq = idx >> 3, p = idx & 7;
    int gq = Q0 + qq;
    float ex = os[qq * 40 + 16 + 3 * p] - __ldg(trans + gq * 3 + 0);
    float ey = os[qq * 40 + 17 + 3 * p] - __ldg(trans + gq * 3 + 1);
    float ez = os[qq * 40 + 18 + 3 * p] - __ldg(trans + gq * 3 + 2);
    const float* R = rot + gq * 9;
    float lx = __ldg(R + 0) * ex + __ldg(R + 3) * ey + __ldg(R + 6) * ez;
    float ly = __ldg(R + 1) * ex + __ldg(R + 4) * ey + __ldg(R + 7) * ez;
    float lz = __ldg(R + 2) * ex + __ldg(R + 5) * ey + __ldg(R + 8) * ez;
    float* cp = g_cat + (size_t)gq * CATW + 192 + h * 8 + p;
    cp[0] = lx;
    cp[96] = ly;
    cp[192] = lz;
    cp[288] = sqrtf(lx * lx + ly * ly + lz * lz + 1e-8f);
  }
}

// ---------------- o_pair (round-8 version — do not touch) ----------------
__global__ __launch_bounds__(256) void k_opair(const float* __restrict__ z) {
  extern __shared__ float sm[];
  float* aT = sm;  // [768][20]
  int t = threadIdx.x;
  int q = blockIdx.x;
#pragma unroll
  for (int h = 0; h < 12; ++h)
    for (int kk = t; kk < N_; kk += 256)
      aT[kk * 20 + h] = g_L[((size_t)h * N_ + q) * N_ + kk];
  __syncthreads();
  int c2 = (t & 63) * 2, kg = t >> 6;
  const float* zq = z + (size_t)q * N_ * CZ;
  u64 acc[12] = {};
#pragma unroll 4
  for (int k = kg; k < N_; k += 4) {
    u64 zd = *(const u64*)(zq + (size_t)k * CZ + c2);
    const float* ar = aT + k * 20;
    float4 a0 = *(const float4*)ar;
    float4 a1 = *(const float4*)(ar + 4);
    float4 a2 = *(const float4*)(ar + 8);
    float av[12] = {a0.x, a0.y, a0.z, a0.w, a1.x, a1.y, a1.z, a1.w,
                    a2.x, a2.y, a2.z, a2.w};
#pragma unroll
    for (int h = 0; h < 12; ++h) fma2(acc[h], zd, pk2(av[h], av[h]));
  }
  __syncthreads();
  u64* buf = (u64*)sm;  // [256][12]
#pragma unroll
  for (int h = 0; h < 12; ++h) buf[t * 12 + h] = acc[h];
  __syncthreads();
  for (int idx = t; idx < 1536; idx += 256) {
    int h = idx >> 7, c = idx & 127;
    float sum = 0.f;
#pragma unroll
    for (int g = 0; g < 4; ++g) {
      float lo, hi;
      upk2(buf[(g * 64 + (c >> 1)) * 12 + h], lo, hi);
      sum += (c & 1) ? hi : lo;
    }
    g_cat[(size_t)q * CATW + 576 + h * 128 + c] = sum;
  }
}

// ---------------- final add ----------------
__global__ void k_add(const float* __restrict__ bo, float* __restrict__ out) {
  int i = blockIdx.x * 256 + threadIdx.x;
  if (i < N_ * CS) {
    int col = i % CS;
    out[i] = g_part[0][i] + g_part[1][i] + g_part[2][i] + __ldg(bo + col);
  }
}

extern "C" void kernel_launch(void* const* d_in, const int* in_sizes, int n_in,
                              void* d_out, int out_size) {
  const float* s     = (const float*)d_in[0];
  const float* z     = (const float*)d_in[1];
  const float* rot   = (const float*)d_in[2];
  const float* trans = (const float*)d_in[3];
  const float* mask  = (const float*)d_in[4];
  const float* w_q   = (const float*)d_in[5];
  const float* b_q   = (const float*)d_in[6];
  const float* w_k   = (const float*)d_in[7];
  const float* b_k   = (const float*)d_in[8];
  const float* w_v   = (const float*)d_in[9];
  const float* b_v   = (const float*)d_in[10];
  const float* w_qp  = (const float*)d_in[11];
  const float* b_qp  = (const float*)d_in[12];
  const float* w_kp  = (const float*)d_in[13];
  const float* b_kp  = (const float*)d_in[14];
  const float* w_vp  = (const float*)d_in[15];
  const float* b_vp  = (const float*)d_in[16];
  const float* w_b   = (const float*)d_in[17];
  const float* b_b   = (const float*)d_in[18];
  const float* hw    = (const float*)d_in[19];
  const float* w_o   = (const float*)d_in[20];
  const float* b_o   = (const float*)d_in[21];
  float* out = (float*)d_out;

  const int BIAS_SMEM = (2 * 16 * 257 + 1536) * 8;  // 78080 bytes

  static bool init_done = false;
  static cudaStream_t s2;
  static cudaEvent_t e_fork1, e_b1, e_b2, e_fork2, e_j2;
  if (!init_done) {
    cudaFuncSetAttribute(k_opair, cudaFuncAttributeMaxDynamicSharedMemorySize, 65536);
    cudaFuncSetAttribute(k_bias7, cudaFuncAttributeMaxDynamicSharedMemorySize, BIAS_SMEM);
    cudaStreamCreateWithFlags(&s2, cudaStreamNonBlocking);
    cudaEventCreateWithFlags(&e_fork1, cudaEventDisableTiming);
    cudaEventCreateWithFlags(&e_b1, cudaEventDisableTiming);
    cudaEventCreateWithFlags(&e_b2, cudaEventDisableTiming);
    cudaEventCreateWithFlags(&e_fork2, cudaEventDisableTiming);
    cudaEventCreateWithFlags(&e_j2, cudaEventDisableTiming);
    init_done = true;
  }

  // Fork 1: bias halves on s2 (memory path); projections on default (compute path).
  cudaEventRecord(e_fork1, 0);
  cudaStreamWaitEvent(s2, e_fork1, 0);
  k_bias7<<<576, 128, BIAS_SMEM, s2>>>(z, w_b, b_b, 0);     // q in [0, 384)
  cudaEventRecord(e_b1, s2);
  k_bias7<<<576, 128, BIAS_SMEM, s2>>>(z, w_b, b_b, 576);   // q in [384, 768)
  cudaEventRecord(e_b2, s2);

  k_pack<<<1728, 256>>>(w_q, w_k, w_v, w_qp, w_kp, w_vp,
                        b_q, b_k, b_v, b_qp, b_kp, b_vp, hw);
  k_gemm1<<<dim3(12, 18), 256>>>(s);
  k_proj<<<N_, 128>>>(rot, trans);

  // logits half 1 overlaps bias half 2
  cudaStreamWaitEvent(0, e_b1, 0);
  k_logits<<<dim3(24, 12), 256>>>(mask, 0);
  cudaStreamWaitEvent(0, e_b2, 0);
  k_logits<<<dim3(24, 12), 256>>>(mask, 24);

  // Fork 2: k_opair on s2 concurrent with k_out (+ gemm2 part A) on default.
  cudaEventRecord(e_fork2, 0);
  cudaStreamWaitEvent(s2, e_fork2, 0);
  k_opair<<<N_, 256, 768 * 20 * 4, s2>>>(z);
  cudaEventRecord(e_j2, s2);

  k_out<<<dim3(24, 12), 160>>>(rot, trans);
  // gemm2 part A reads g_cat cols [0,576) — produced only by k_out.
  k_gemm2<<<dim3(12, 6), 256>>>(w_o, 0, 36, 0);
  cudaStreamWaitEvent(0, e_j2, 0);
  // parts B/C read cols [576,2112) — produced by k_opair.
  k_gemm2<<<dim3(12, 6), 256>>>(w_o, 36, 48, 1);
  k_gemm2<<<dim3(12, 6), 256>>>(w_o, 84, 48, 2);
  k_add<<<1152, 256>>>(b_o, out);
}

// round 14
// speedup vs baseline: 1.0590x; 1.0201x over previous
#include <cuda_runtime.h>
#include <math.h>

#define N_ 768
#define CS 384
#define CZ 128
#define NH 12
#define LINW 1152
#define CATW 2112
#define INF_ 100000.0f
#define NK_ ((size_t)N_ * N_)   // 589824

// ---------------- device scratch ----------------
__device__ float g_wpack[CS * LINW];
__device__ float g_bpack[LINW];
__device__ float g_pw[NH];
__device__ float g_lin[N_ * LINW];
__device__ float g_qops[NH * N_ * 32];
__device__ float g_kops[NH * N_ * 32];
__device__ float g_vops[NH * N_ * 40];
__device__ float g_L[NH * NK_];
__device__ float g_cat[N_ * CATW];
__device__ float g_part[3][N_ * CS];

// ---------------- f32x2 helpers ----------------
typedef unsigned long long u64;
__device__ __forceinline__ u64 pk2(float a, float b) {
  u64 r;
  asm("mov.b64 %0, {%1,%2};" : "=l"(r) : "f"(a), "f"(b));
  return r;
}
__device__ __forceinline__ void upk2(u64 v, float& a, float& b) {
  asm("mov.b64 {%0,%1}, %2;" : "=f"(a), "=f"(b) : "l"(v));
}
__device__ __forceinline__ void fma2(u64& d, u64 a, u64 b) {
  asm("fma.rn.f32x2 %0, %1, %2, %0;" : "+l"(d) : "l"(a), "l"(b));
}

// ---------------- pack weights ----------------
__global__ void k_pack(const float* wq, const float* wk, const float* wv,
                       const float* wqp, const float* wkp, const float* wvp,
                       const float* bq, const float* bk, const float* bv,
                       const float* bqp, const float* bkp, const float* bvp,
                       const float* hw) {
  int idx = blockIdx.x * 256 + threadIdx.x;
  if (idx < CS * LINW) {
    int i = idx / LINW, j = idx - i * LINW;
    float v;
    if (j < 192)       v = wq[i * 192 + j];
    else if (j < 384)  v = wk[i * 192 + j - 192];
    else if (j < 576)  v = wv[i * 192 + j - 384];
    else if (j < 720)  v = wqp[i * 144 + j - 576];
    else if (j < 864)  v = wkp[i * 144 + j - 720];
    else               v = wvp[i * 288 + j - 864];
    g_wpack[idx] = v;
  }
  if (idx < LINW) {
    int j = idx;
    float v;
    if (j < 192)       v = bq[j];
    else if (j < 384)  v = bk[j - 192];
    else if (j < 576)  v = bv[j - 384];
    else if (j < 720)  v = bqp[j - 576];
    else if (j < 864)  v = bkp[j - 720];
    else               v = bvp[j - 864];
    g_bpack[j] = v;
  }
  if (idx < NH) {
    float h = hw[idx];
    g_pw[idx] = 0.23570226039551584f * (fmaxf(h, 0.f) + log1pf(expf(-fabsf(h))));
  }
}

// ---------------- GEMM 1: g_lin = s @ wpack (768x1152, K=384), pipelined ----------------
__global__ __launch_bounds__(256) void k_gemm1(const float* __restrict__ A) {
  __shared__ float aT[16][68];
  __shared__ float bT[16][68];
  int m0 = blockIdx.x * 64, n0 = blockIdx.y * 64;
  int t = threadIdx.x;
  int mi = (t & 15) * 4, ni = (t >> 4) * 4;
  u64 c2[4][2] = {};
  float a_pf[4], b_pf[4];
#pragma unroll
  for (int j = 0; j < 4; ++j) {
    int e = t + j * 256;
    a_pf[j] = A[(m0 + (e >> 4)) * CS + (e & 15)];
    b_pf[j] = g_wpack[(e >> 6) * LINW + n0 + (e & 63)];
  }
  for (int kt = 0; kt < 24; ++kt) {
    __syncthreads();
#pragma unroll
    for (int j = 0; j < 4; ++j) {
      int e = t + j * 256;
      aT[e & 15][e >> 4] = a_pf[j];
      bT[e >> 6][e & 63] = b_pf[j];
    }
    if (kt + 1 < 24) {
      int k0 = (kt + 1) * 16;
#pragma unroll
      for (int j = 0; j < 4; ++j) {
        int e = t + j * 256;
        a_pf[j] = A[(m0 + (e >> 4)) * CS + k0 + (e & 15)];
        b_pf[j] = g_wpack[(k0 + (e >> 6)) * LINW + n0 + (e & 63)];
      }
    }
    __syncthreads();
#pragma unroll
    for (int kk = 0; kk < 16; ++kk) {
      float4 a = *(const float4*)&aT[kk][mi];
      float4 b = *(const float4*)&bT[kk][ni];
      u64 b0 = pk2(b.x, b.y), b1 = pk2(b.z, b.w);
      u64 a0 = pk2(a.x, a.x), a1 = pk2(a.y, a.y), a2 = pk2(a.z, a.z), a3 = pk2(a.w, a.w);
      fma2(c2[0][0], a0, b0); fma2(c2[0][1], a0, b1);
      fma2(c2[1][0], a1, b0); fma2(c2[1][1], a1, b1);
      fma2(c2[2][0], a2, b0); fma2(c2[2][1], a2, b1);
      fma2(c2[3][0], a3, b0); fma2(c2[3][1], a3, b1);
    }
  }
#pragma unroll
  for (int r = 0; r < 4; ++r)
#pragma unroll
    for (int j = 0; j < 2; ++j) {
      float lo, hi;
      upk2(c2[r][j], lo, hi);
      g_lin[(m0 + mi + r) * LINW + n0 + ni + 2 * j] = lo;
      g_lin[(m0 + mi + r) * LINW + n0 + ni + 2 * j + 1] = hi;
    }
}

// ---------------- GEMM 2: part[part] = cat[:, 16*kstart : 16*(kstart+ntiles)] @ w_o ----------------
__global__ __launch_bounds__(256) void k_gemm2(const float* __restrict__ B,
                                               int kstart, int ntiles, int part) {
  __shared__ float aT[16][68];
  __shared__ float bT[16][68];
  int m0 = blockIdx.x * 64, n0 = blockIdx.y * 64;
  int t = threadIdx.x;
  int mi = (t & 15) * 4, ni = (t >> 4) * 4;
  u64 c2[4][2] = {};
  int kbase = kstart * 16;
  float a_pf[4], b_pf[4];
#pragma unroll
  for (int j = 0; j < 4; ++j) {
    int e = t + j * 256;
    a_pf[j] = g_cat[(m0 + (e >> 4)) * CATW + kbase + (e & 15)];
    b_pf[j] = B[(kbase + (e >> 6)) * CS + n0 + (e & 63)];
  }
  for (int kt = 0; kt < ntiles; ++kt) {
    __syncthreads();
#pragma unroll
    for (int j = 0; j < 4; ++j) {
      int e = t + j * 256;
      aT[e & 15][e >> 4] = a_pf[j];
      bT[e >> 6][e & 63] = b_pf[j];
    }
    if (kt + 1 < ntiles) {
      int k0 = kbase + (kt + 1) * 16;
#pragma unroll
      for (int j = 0; j < 4; ++j) {
        int e = t + j * 256;
        a_pf[j] = g_cat[(m0 + (e >> 4)) * CATW + k0 + (e & 15)];
        b_pf[j] = B[(k0 + (e >> 6)) * CS + n0 + (e & 63)];
      }
    }
    __syncthreads();
#pragma unroll
    for (int kk = 0; kk < 16; ++kk) {
      float4 a = *(const float4*)&aT[kk][mi];
      float4 b = *(const float4*)&bT[kk][ni];
      u64 b0 = pk2(b.x, b.y), b1 = pk2(b.z, b.w);
      u64 a0 = pk2(a.x, a.x), a1 = pk2(a.y, a.y), a2 = pk2(a.z, a.z), a3 = pk2(a.w, a.w);
      fma2(c2[0][0], a0, b0); fma2(c2[0][1], a0, b1);
      fma2(c2[1][0], a1, b0); fma2(c2[1][1], a1, b1);
      fma2(c2[2][0], a2, b0); fma2(c2[2][1], a2, b1);
      fma2(c2[3][0], a3, b0); fma2(c2[3][1], a3, b1);
    }
  }
  float* outp = &g_part[part][0];
#pragma unroll
  for (int r = 0; r < 4; ++r)
#pragma unroll
    for (int j = 0; j < 2; ++j) {
      float lo, hi;
      upk2(c2[r][j], lo, hi);
      outp[(m0 + mi + r) * CS + n0 + ni + 2 * j] = lo;
      outp[(m0 + mi + r) * CS + n0 + ni + 2 * j + 1] = hi;
    }
}

// ---------------- projection epilogue per residue ----------------
__global__ __launch_bounds__(128) void k_proj(const float* __restrict__ rot,
                                              const float* __restrict__ trans) {
  __shared__ float s2[24];
  int q = blockIdx.x, t = threadIdx.x;
  const float* lin = g_lin + q * LINW;
  if (t < 24) s2[t] = 0.f;
  __syncthreads();
  float R[9], tr[3];
#pragma unroll
  for (int j = 0; j < 9; ++j) R[j] = __ldg(rot + q * 9 + j);
#pragma unroll
  for (int j = 0; j < 3; ++j) tr[j] = __ldg(trans + q * 3 + j);
  for (int i = t; i < 192; i += 128) {
    int h = i >> 4, c = i & 15;
    g_qops[(h * N_ + q) * 32 + c] = (lin[i] + g_bpack[i]) * 0.25f;
    g_kops[(h * N_ + q) * 32 + c] = lin[192 + i] + g_bpack[192 + i];
    g_vops[(h * N_ + q) * 40 + c] = lin[384 + i] + g_bpack[384 + i];
  }
  if (t < 96) {
    int which = t / 48;
    int i = t % 48;
    int h = i >> 2, p = i & 3;
    int base = 576 + which * 144 + h * 12;
    float lx = lin[base + p] + g_bpack[base + p];
    float ly = lin[base + 4 + p] + g_bpack[base + 4 + p];
    float lz = lin[base + 8 + p] + g_bpack[base + 8 + p];
    float gx = R[0] * lx + R[1] * ly + R[2] * lz + tr[0];
    float gy = R[3] * lx + R[4] * ly + R[5] * lz + tr[1];
    float gz = R[6] * lx + R[7] * ly + R[8] * lz + tr[2];
    float n2 = gx * gx + gy * gy + gz * gz;
    int o = (h * N_ + q) * 32 + 16 + p * 3;
    if (which == 0) {
      g_qops[o] = gx; g_qops[o + 1] = gy; g_qops[o + 2] = gz;
      atomicAdd(&s2[h], n2);
    } else {
      g_kops[o] = gx; g_kops[o + 1] = gy; g_kops[o + 2] = gz;
      atomicAdd(&s2[12 + h], n2);
    }
  }
  if (t < 96) {
    int h = t >> 3, p = t & 7;
    int base = 864 + h * 24;
    float lx = lin[base + p] + g_bpack[base + p];
    float ly = lin[base + 8 + p] + g_bpack[base + 8 + p];
    float lz = lin[base + 16 + p] + g_bpack[base + 16 + p];
    float gx = R[0] * lx + R[1] * ly + R[2] * lz + tr[0];
    float gy = R[3] * lx + R[4] * ly + R[5] * lz + tr[1];
    float gz = R[6] * lx + R[7] * ly + R[8] * lz + tr[2];
    int o = (h * N_ + q) * 40 + 16 + p * 3;
    g_vops[o] = gx; g_vops[o + 1] = gy; g_vops[o + 2] = gz;
  }
  __syncthreads();
  if (t < 12) {
    g_qops[(t * N_ + q) * 32 + 28] = s2[t];
    g_kops[(t * N_ + q) * 32 + 28] = s2[12 + t];
  }
}

// ---------------- pair bias (k_bias7, round-8/10 proven version) ----------------
__global__ __launch_bounds__(128) void k_bias7(const float* __restrict__ z,
                                               const float* __restrict__ wb,
                                               const float* __restrict__ bb) {
  extern __shared__ u64 sm7[];
  u64* zb0 = sm7;
  u64* zb1 = sm7 + 16 * 257;
  u64* w2 = sm7 + 2 * 16 * 257;
  int t = threadIdx.x;
  for (int idx = t; idx < 1536; idx += 128) {
    int c = idx / 12, h = idx - c * 12;
    float w = __ldg(wb + c * 12 + h);
    w2[idx] = pk2(w, w);
  }
  size_t R0 = (size_t)blockIdx.x * 512;

  float4 vA[8], vB[8];
#pragma unroll
  for (int i = 0; i < 8; ++i) {
    int idx = t + i * 128;
    int rp = idx >> 2, j = idx & 3;
    const float* pA = z + (R0 + rp) * CZ + 4 * j;
    vA[i] = *(const float4*)pA;
    vB[i] = *(const float4*)(pA + 256 * CZ);
  }
#pragma unroll
  for (int i = 0; i < 8; ++i) {
    int idx = t + i * 128;
    int rp = idx >> 2, j = idx & 3;
    u64* d = zb0 + 4 * j * 257 + rp;
    d[0] = pk2(vA[i].x, vB[i].x);
    d[257] = pk2(vA[i].y, vB[i].y);
    d[514] = pk2(vA[i].z, vB[i].z);
    d[771] = pk2(vA[i].w, vB[i].w);
  }
  __syncthreads();

  u64 acc0[12] = {}, acc1[12] = {};
  for (int ch = 0; ch < 8; ++ch) {
    u64* cur = (ch & 1) ? zb1 : zb0;
    u64* nxt = (ch & 1) ? zb0 : zb1;
    if (ch < 7) {
#pragma unroll
      for (int i = 0; i < 8; ++i) {
        int idx = t + i * 128;
        int rp = idx >> 2, j = idx & 3;
        const float* pA = z + (R0 + rp) * CZ + (ch + 1) * 16 + 4 * j;
        vA[i] = *(const float4*)pA;
        vB[i] = *(const float4*)(pA + 256 * CZ);
      }
    }
    const u64* w2c = w2 + ch * 16 * 12;
#pragma unroll
    for (int cl = 0; cl < 16; ++cl) {
      u64 z0 = cur[cl * 257 + t];
      u64 z1 = cur[cl * 257 + t + 128];
      const u64* wr = w2c + cl * 12;
#pragma unroll
      for (int h = 0; h < 12; ++h) {
        u64 w = wr[h];
        fma2(acc0[h], z0, w);
        fma2(acc1[h], z1, w);
      }
    }
    if (ch < 7) {
#pragma unroll
      for (int i = 0; i < 8; ++i) {
        int idx = t + i * 128;
        int rp = idx >> 2, j = idx & 3;
        u64* d = nxt + 4 * j * 257 + rp;
        d[0] = pk2(vA[i].x, vB[i].x);
        d[257] = pk2(vA[i].y, vB[i].y);
        d[514] = pk2(vA[i].z, vB[i].z);
        d[771] = pk2(vA[i].w, vB[i].w);
      }
    }
    __syncthreads();
  }
#pragma unroll
  for (int h = 0; h < 12; ++h) {
    float bbh = __ldg(bb + h);
    float a, b, c, d;
    upk2(acc0[h], a, b);
    upk2(acc1[h], c, d);
    float* Lp = g_L + (size_t)h * NK_ + R0;
    Lp[t] = a + bbh;
    Lp[t + 256] = b + bbh;
    Lp[t + 128] = c + bbh;
    Lp[t + 384] = d + bbh;
  }
}

// ---------------- logits + softmax (in place on g_L) ----------------
__global__ __launch_bounds__(256) void k_logits(const float* __restrict__ mask) {
  __shared__ float ks[256 * 36];
  int t = threadIdx.x;
  int h = blockIdx.y;
  int Q0 = blockIdx.x * 16;
  int ql = t >> 4, s = t & 15;
  int q = Q0 + ql;
  const float* qop = g_qops + ((size_t)h * N_ + q) * 32;
  const u64* qop8 = (const u64*)qop;
  u64 qh_u[8], qp_u[6];
#pragma unroll
  for (int i = 0; i < 8; ++i) qh_u[i] = qop8[i];
#pragma unroll
  for (int i = 0; i < 6; ++i) qp_u[i] = qop8[8 + i];
  float q2 = qop[28];
  float pw = g_pw[h];
  float cb = -0.5f * pw * q2;
  float mq = __ldg(mask + q);
  const float* Lrow = g_L + ((size_t)h * N_ + q) * N_;
  float lg[48];
#pragma unroll
  for (int ch = 0; ch < 3; ++ch) {
    int k0 = ch * 256;
    __syncthreads();
#pragma unroll
    for (int i = 0; i < 8; ++i) {
      int idx = t + i * 256;
      int row = idx >> 3, f4 = idx & 7;
      *(float4*)(ks + row * 36 + f4 * 4) =
          *(const float4*)(g_kops + ((size_t)h * N_ + k0 + row) * 32 + f4 * 4);
    }
    __syncthreads();
#pragma unroll
    for (int jj = 0; jj < 16; ++jj) {
      int kl = s + 16 * jj;
      const u64* kr8 = (const u64*)(ks + kl * 36);
      u64 d2 = 0, e2 = 0;
#pragma unroll
      for (int i = 0; i < 8; ++i) fma2(d2, kr8[i], qh_u[i]);
#pragma unroll
      for (int i = 0; i < 6; ++i) fma2(e2, kr8[8 + i], qp_u[i]);
      float dlo, dhi, elo, ehi;
      upk2(d2, dlo, dhi);
      upk2(e2, elo, ehi);
      float k2s = ks[kl * 36 + 28];
      int k = k0 + kl;
      lg[ch * 16 + jj] = Lrow[k] + dlo + dhi + pw * (elo + ehi - 0.5f * k2s) + cb
                         + INF_ * (mq * __ldg(mask + k) - 1.f);
    }
  }
  float mx = -3.0e38f;
#pragma unroll
  for (int i = 0; i < 48; ++i) mx = fmaxf(mx, lg[i]);
  mx = fmaxf(mx, __shfl_xor_sync(0xffffffffu, mx, 1));
  mx = fmaxf(mx, __shfl_xor_sync(0xffffffffu, mx, 2));
  mx = fmaxf(mx, __shfl_xor_sync(0xffffffffu, mx, 4));
  mx = fmaxf(mx, __shfl_xor_sync(0xffffffffu, mx, 8));
  float sum = 0.f;
#pragma unroll
  for (int i = 0; i < 48; ++i) {
    float w = __expf(0.57735026919f * (lg[i] - mx));
    lg[i] = w;
    sum += w;
  }
  sum += __shfl_xor_sync(0xffffffffu, sum, 1);
  sum += __shfl_xor_sync(0xffffffffu, sum, 2);
  sum += __shfl_xor_sync(0xffffffffu, sum, 4);
  sum += __shfl_xor_sync(0xffffffffu, sum, 8);
  float inv = 1.f / sum;
  float* Lw = g_L + ((size_t)h * N_ + q) * N_;
#pragma unroll
  for (int ch = 0; ch < 3; ++ch)
#pragma unroll
    for (int jj = 0; jj < 16; ++jj)
      Lw[ch * 256 + s + 16 * jj] = lg[ch * 16 + jj] * inv;
}

// ---------------- o + o_pt + norms ----------------
__global__ __launch_bounds__(160) void k_out(const float* __restrict__ rot,
                                             const float* __restrict__ trans) {
  __shared__ float as[32 * 132];
  __shared__ float vs[128 * 44];
  __shared__ float os[32 * 40];
  int t = threadIdx.x;
  int h = blockIdx.y;
  int Q0 = blockIdx.x * 32;
  int q = t / 5, s = t - q * 5;
  u64 acc2[4] = {};
  for (int ch = 0; ch < 6; ++ch) {
    int k0 = ch * 128;
    __syncthreads();
    for (int idx = t; idx < 1024; idx += 160) {
      int qq = idx >> 5, f4 = idx & 31;
      *(float4*)(as + qq * 132 + f4 * 4) =
          *(const float4*)(g_L + ((size_t)h * N_ + Q0 + qq) * N_ + k0 + f4 * 4);
    }
    for (int idx = t; idx < 1280; idx += 160) {
      int row = idx / 10, f4 = idx - row * 10;
      *(float4*)(vs + row * 44 + f4 * 4) =
          *(const float4*)(g_vops + ((size_t)h * N_ + k0 + row) * 40 + f4 * 4);
    }
    __syncthreads();
#pragma unroll 4
    for (int kl = 0; kl < 128; ++kl) {
      float a = as[q * 132 + kl];
      u64 au = pk2(a, a);
      const u64* vp = (const u64*)(vs + kl * 44 + 8 * s);
      fma2(acc2[0], vp[0], au);
      fma2(acc2[1], vp[1], au);
      fma2(acc2[2], vp[2], au);
      fma2(acc2[3], vp[3], au);
    }
  }
#pragma unroll
  for (int i = 0; i < 4; ++i) {
    float lo, hi;
    upk2(acc2[i], lo, hi);
    os[q * 40 + 8 * s + 2 * i] = lo;
    os[q * 40 + 8 * s + 2 * i + 1] = hi;
  }
  __syncthreads();
  for (int idx = t; idx < 512; idx += 160) {
    int qq = idx >> 4, c = idx & 15;
    g_cat[(size_t)(Q0 + qq) * CATW + h * 16 + c] = os[qq * 40 + c];
  }
  for (int idx = t; idx < 256; idx += 160) {
    int qq = idx >> 3, p = idx & 7;
    int gq = Q0 + qq;
    float ex = os[qq * 40 + 16 + 3 * p] - __ldg(trans + gq * 3 + 0);
    float ey = os[qq * 40 + 17 + 3 * p] - __ldg(trans + gq * 3 + 1);
    float ez = os[qq * 40 + 18 + 3 * p] - __ldg(trans + gq * 3 + 2);
    const float* R = rot + gq * 9;
    float lx = __ldg(R + 0) * ex + __ldg(R + 3) * ey + __ldg(R + 6) * ez;
    float ly = __ldg(R + 1) * ex + __ldg(R + 4) * ey + __ldg(R + 7) * ez;
    float lz = __ldg(R + 2) * ex + __ldg(R + 5) * ey + __ldg(R + 8) * ez;
    float* cp = g_cat + (size_t)gq * CATW + 192 + h * 8 + p;
    cp[0] = lx;
    cp[96] = ly;
    cp[192] = lz;
    cp[288] = sqrtf(lx * lx + ly * ly + lz * lz + 1e-8f);
  }
}

// ---------------- o_pair (round-8 version — do not touch) ----------------
__global__ __launch_bounds__(256) void k_opair(const float* __restrict__ z) {
  extern __shared__ float sm[];
  float* aT = sm;  // [768][20]
  int t = threadIdx.x;
  int q = blockIdx.x;
#pragma unroll
  for (int h = 0; h < 12; ++h)
    for (int kk = t; kk < N_; kk += 256)
      aT[kk * 20 + h] = g_L[((size_t)h * N_ + q) * N_ + kk];
  __syncthreads();
  int c2 = (t & 63) * 2, kg = t >> 6;
  const float* zq = z + (size_t)q * N_ * CZ;
  u64 acc[12] = {};
#pragma unroll 4
  for (int k = kg; k < N_; k += 4) {
    u64 zd = *(const u64*)(zq + (size_t)k * CZ + c2);
    const float* ar = aT + k * 20;
    float4 a0 = *(const float4*)ar;
    float4 a1 = *(const float4*)(ar + 4);
    float4 a2 = *(const float4*)(ar + 8);
    float av[12] = {a0.x, a0.y, a0.z, a0.w, a1.x, a1.y, a1.z, a1.w,
                    a2.x, a2.y, a2.z, a2.w};
#pragma unroll
    for (int h = 0; h < 12; ++h) fma2(acc[h], zd, pk2(av[h], av[h]));
  }
  __syncthreads();
  u64* buf = (u64*)sm;  // [256][12]
#pragma unroll
  for (int h = 0; h < 12; ++h) buf[t * 12 + h] = acc[h];
  __syncthreads();
  for (int idx = t; idx < 1536; idx += 256) {
    int h = idx >> 7, c = idx & 127;
    float sum = 0.f;
#pragma unroll
    for (int g = 0; g < 4; ++g) {
      float lo, hi;
      upk2(buf[(g * 64 + (c >> 1)) * 12 + h], lo, hi);
      sum += (c & 1) ? hi : lo;
    }
    g_cat[(size_t)q * CATW + 576 + h * 128 + c] = sum;
  }
}

// ---------------- final add ----------------
__global__ void k_add(const float* __restrict__ bo, float* __restrict__ out) {
  int i = blockIdx.x * 256 + threadIdx.x;
  if (i < N_ * CS) {
    int col = i % CS;
    out[i] = g_part[0][i] + g_part[1][i] + g_part[2][i] + __ldg(bo + col);
  }
}

extern "C" void kernel_launch(void* const* d_in, const int* in_sizes, int n_in,
                              void* d_out, int out_size) {
  const float* s     = (const float*)d_in[0];
  const float* z     = (const float*)d_in[1];
  const float* rot   = (const float*)d_in[2];
  const float* trans = (const float*)d_in[3];
  const float* mask  = (const float*)d_in[4];
  const float* w_q   = (const float*)d_in[5];
  const float* b_q   = (const float*)d_in[6];
  const float* w_k   = (const float*)d_in[7];
  const float* b_k   = (const float*)d_in[8];
  const float* w_v   = (const float*)d_in[9];
  const float* b_v   = (const float*)d_in[10];
  const float* w_qp  = (const float*)d_in[11];
  const float* b_qp  = (const float*)d_in[12];
  const float* w_kp  = (const float*)d_in[13];
  const float* b_kp  = (const float*)d_in[14];
  const float* w_vp  = (const float*)d_in[15];
  const float* b_vp  = (const float*)d_in[16];
  const float* w_b   = (const float*)d_in[17];
  const float* b_b   = (const float*)d_in[18];
  const float* hw    = (const float*)d_in[19];
  const float* w_o   = (const float*)d_in[20];
  const float* b_o   = (const float*)d_in[21];
  float* out = (float*)d_out;

  const int BIAS_SMEM = (2 * 16 * 257 + 1536) * 8;  // 78080 bytes

  static bool init_done = false;
  static cudaStream_t s2, s3;
  static cudaEvent_t e_fork1, e_join1, e_fork2, e_j2, e_fork3, e_c;
  if (!init_done) {
    cudaFuncSetAttribute(k_opair, cudaFuncAttributeMaxDynamicSharedMemorySize, 65536);
    cudaFuncSetAttribute(k_bias7, cudaFuncAttributeMaxDynamicSharedMemorySize, BIAS_SMEM);
    cudaStreamCreateWithFlags(&s2, cudaStreamNonBlocking);
    cudaStreamCreateWithFlags(&s3, cudaStreamNonBlocking);
    cudaEventCreateWithFlags(&e_fork1, cudaEventDisableTiming);
    cudaEventCreateWithFlags(&e_join1, cudaEventDisableTiming);
    cudaEventCreateWithFlags(&e_fork2, cudaEventDisableTiming);
    cudaEventCreateWithFlags(&e_j2, cudaEventDisableTiming);
    cudaEventCreateWithFlags(&e_fork3, cudaEventDisableTiming);
    cudaEventCreateWithFlags(&e_c, cudaEventDisableTiming);
    init_done = true;
  }

  // Fork 1: bias (memory path) on s2; projections (compute path) on default.
  cudaEventRecord(e_fork1, 0);
  cudaStreamWaitEvent(s2, e_fork1, 0);
  k_bias7<<<1152, 128, BIAS_SMEM, s2>>>(z, w_b, b_b);
  cudaEventRecord(e_join1, s2);

  k_pack<<<1728, 256>>>(w_q, w_k, w_v, w_qp, w_kp, w_vp,
                        b_q, b_k, b_v, b_qp, b_kp, b_vp, hw);
  k_gemm1<<<dim3(12, 18), 256>>>(s);
  k_proj<<<N_, 128>>>(rot, trans);
  cudaStreamWaitEvent(0, e_join1, 0);

  k_logits<<<dim3(48, 12), 256>>>(mask);

  // Fork 2: k_opair on s2 concurrent with k_out + gemm2 part A on default.
  cudaEventRecord(e_fork2, 0);
  cudaStreamWaitEvent(s2, e_fork2, 0);
  k_opair<<<N_, 256, 768 * 20 * 4, s2>>>(z);
  cudaEventRecord(e_j2, s2);

  k_out<<<dim3(24, 12), 160>>>(rot, trans);
  // Part A reads g_cat cols [0,576) — produced only by k_out; overlaps k_opair.
  k_gemm2<<<dim3(12, 6), 256>>>(w_o, 0, 36, 0);

  // Parts B and C read cols [576,2112) — produced by k_opair. Run B ∥ C.
  cudaStreamWaitEvent(0, e_j2, 0);
  cudaEventRecord(e_fork3, 0);
  cudaStreamWaitEvent(s3, e_fork3, 0);
  k_gemm2<<<dim3(12, 6), 256, 0, s3>>>(w_o, 84, 48, 2);
  cudaEventRecord(e_c, s3);

  k_gemm2<<<dim3(12, 6), 256>>>(w_o, 36, 48, 1);
  cudaStreamWaitEvent(0, e_c, 0);
  k_add<<<1152, 256>>>(b_o, out);
}

// round 15
// speedup vs baseline: 1.0879x; 1.0273x over previous
#include <cuda_runtime.h>
#include <math.h>

#define N_ 768
#define CS 384
#define CZ 128
#define NH 12
#define LINW 1152
#define CATW 2112
#define INF_ 100000.0f
#define NK_ ((size_t)N_ * N_)   // 589824

// ---------------- device scratch ----------------
__device__ float g_wpack[CS * LINW];
__device__ float g_bpack[LINW];
__device__ float g_pw[NH];
__device__ float g_lin[N_ * LINW];
__device__ float g_qops[NH * N_ * 32];
__device__ float g_kops[NH * N_ * 32];
__device__ float g_vops[NH * N_ * 40];
__device__ float g_L[NH * NK_];
__device__ float g_cat[N_ * CATW];
__device__ float g_part[3][N_ * CS];

// ---------------- f32x2 helpers ----------------
typedef unsigned long long u64;
__device__ __forceinline__ u64 pk2(float a, float b) {
  u64 r;
  asm("mov.b64 %0, {%1,%2};" : "=l"(r) : "f"(a), "f"(b));
  return r;
}
__device__ __forceinline__ void upk2(u64 v, float& a, float& b) {
  asm("mov.b64 {%0,%1}, %2;" : "=f"(a), "=f"(b) : "l"(v));
}
__device__ __forceinline__ void fma2(u64& d, u64 a, u64 b) {
  asm("fma.rn.f32x2 %0, %1, %2, %0;" : "+l"(d) : "l"(a), "l"(b));
}

// ---------------- pack weights ----------------
__global__ void k_pack(const float* wq, const float* wk, const float* wv,
                       const float* wqp, const float* wkp, const float* wvp,
                       const float* bq, const float* bk, const float* bv,
                       const float* bqp, const float* bkp, const float* bvp,
                       const float* hw) {
  int idx = blockIdx.x * 256 + threadIdx.x;
  if (idx < CS * LINW) {
    int i = idx / LINW, j = idx - i * LINW;
    float v;
    if (j < 192)       v = wq[i * 192 + j];
    else if (j < 384)  v = wk[i * 192 + j - 192];
    else if (j < 576)  v = wv[i * 192 + j - 384];
    else if (j < 720)  v = wqp[i * 144 + j - 576];
    else if (j < 864)  v = wkp[i * 144 + j - 720];
    else               v = wvp[i * 288 + j - 864];
    g_wpack[idx] = v;
  }
  if (idx < LINW) {
    int j = idx;
    float v;
    if (j < 192)       v = bq[j];
    else if (j < 384)  v = bk[j - 192];
    else if (j < 576)  v = bv[j - 384];
    else if (j < 720)  v = bqp[j - 576];
    else if (j < 864)  v = bkp[j - 720];
    else               v = bvp[j - 864];
    g_bpack[j] = v;
  }
  if (idx < NH) {
    float h = hw[idx];
    g_pw[idx] = 0.23570226039551584f * (fmaxf(h, 0.f) + log1pf(expf(-fabsf(h))));
  }
}

// ---------------- GEMM 1: g_lin = s @ wpack (768x1152, K=384), pipelined ----------------
__global__ __launch_bounds__(256) void k_gemm1(const float* __restrict__ A) {
  __shared__ float aT[16][68];
  __shared__ float bT[16][68];
  int m0 = blockIdx.x * 64, n0 = blockIdx.y * 64;
  int t = threadIdx.x;
  int mi = (t & 15) * 4, ni = (t >> 4) * 4;
  u64 c2[4][2] = {};
  float a_pf[4], b_pf[4];
#pragma unroll
  for (int j = 0; j < 4; ++j) {
    int e = t + j * 256;
    a_pf[j] = A[(m0 + (e >> 4)) * CS + (e & 15)];
    b_pf[j] = g_wpack[(e >> 6) * LINW + n0 + (e & 63)];
  }
  for (int kt = 0; kt < 24; ++kt) {
    __syncthreads();
#pragma unroll
    for (int j = 0; j < 4; ++j) {
      int e = t + j * 256;
      aT[e & 15][e >> 4] = a_pf[j];
      bT[e >> 6][e & 63] = b_pf[j];
    }
    if (kt + 1 < 24) {
      int k0 = (kt + 1) * 16;
#pragma unroll
      for (int j = 0; j < 4; ++j) {
        int e = t + j * 256;
        a_pf[j] = A[(m0 + (e >> 4)) * CS + k0 + (e & 15)];
        b_pf[j] = g_wpack[(k0 + (e >> 6)) * LINW + n0 + (e & 63)];
      }
    }
    __syncthreads();
#pragma unroll
    for (int kk = 0; kk < 16; ++kk) {
      float4 a = *(const float4*)&aT[kk][mi];
      float4 b = *(const float4*)&bT[kk][ni];
      u64 b0 = pk2(b.x, b.y), b1 = pk2(b.z, b.w);
      u64 a0 = pk2(a.x, a.x), a1 = pk2(a.y, a.y), a2 = pk2(a.z, a.z), a3 = pk2(a.w, a.w);
      fma2(c2[0][0], a0, b0); fma2(c2[0][1], a0, b1);
      fma2(c2[1][0], a1, b0); fma2(c2[1][1], a1, b1);
      fma2(c2[2][0], a2, b0); fma2(c2[2][1], a2, b1);
      fma2(c2[3][0], a3, b0); fma2(c2[3][1], a3, b1);
    }
  }
#pragma unroll
  for (int r = 0; r < 4; ++r)
#pragma unroll
    for (int j = 0; j < 2; ++j) {
      float lo, hi;
      upk2(c2[r][j], lo, hi);
      g_lin[(m0 + mi + r) * LINW + n0 + ni + 2 * j] = lo;
      g_lin[(m0 + mi + r) * LINW + n0 + ni + 2 * j + 1] = hi;
    }
}

// ---------------- GEMM 2: part[part] = cat[:, 16*kstart : 16*(kstart+ntiles)] @ w_o ----------------
__global__ __launch_bounds__(256) void k_gemm2(const float* __restrict__ B,
                                               int kstart, int ntiles, int part) {
  __shared__ float aT[16][68];
  __shared__ float bT[16][68];
  int m0 = blockIdx.x * 64, n0 = blockIdx.y * 64;
  int t = threadIdx.x;
  int mi = (t & 15) * 4, ni = (t >> 4) * 4;
  u64 c2[4][2] = {};
  int kbase = kstart * 16;
  float a_pf[4], b_pf[4];
#pragma unroll
  for (int j = 0; j < 4; ++j) {
    int e = t + j * 256;
    a_pf[j] = g_cat[(m0 + (e >> 4)) * CATW + kbase + (e & 15)];
    b_pf[j] = B[(kbase + (e >> 6)) * CS + n0 + (e & 63)];
  }
  for (int kt = 0; kt < ntiles; ++kt) {
    __syncthreads();
#pragma unroll
    for (int j = 0; j < 4; ++j) {
      int e = t + j * 256;
      aT[e & 15][e >> 4] = a_pf[j];
      bT[e >> 6][e & 63] = b_pf[j];
    }
    if (kt + 1 < ntiles) {
      int k0 = kbase + (kt + 1) * 16;
#pragma unroll
      for (int j = 0; j < 4; ++j) {
        int e = t + j * 256;
        a_pf[j] = g_cat[(m0 + (e >> 4)) * CATW + k0 + (e & 15)];
        b_pf[j] = B[(k0 + (e >> 6)) * CS + n0 + (e & 63)];
      }
    }
    __syncthreads();
#pragma unroll
    for (int kk = 0; kk < 16; ++kk) {
      float4 a = *(const float4*)&aT[kk][mi];
      float4 b = *(const float4*)&bT[kk][ni];
      u64 b0 = pk2(b.x, b.y), b1 = pk2(b.z, b.w);
      u64 a0 = pk2(a.x, a.x), a1 = pk2(a.y, a.y), a2 = pk2(a.z, a.z), a3 = pk2(a.w, a.w);
      fma2(c2[0][0], a0, b0); fma2(c2[0][1], a0, b1);
      fma2(c2[1][0], a1, b0); fma2(c2[1][1], a1, b1);
      fma2(c2[2][0], a2, b0); fma2(c2[2][1], a2, b1);
      fma2(c2[3][0], a3, b0); fma2(c2[3][1], a3, b1);
    }
  }
  float* outp = &g_part[part][0];
#pragma unroll
  for (int r = 0; r < 4; ++r)
#pragma unroll
    for (int j = 0; j < 2; ++j) {
      float lo, hi;
      upk2(c2[r][j], lo, hi);
      outp[(m0 + mi + r) * CS + n0 + ni + 2 * j] = lo;
      outp[(m0 + mi + r) * CS + n0 + ni + 2 * j + 1] = hi;
    }
}

// ---------------- projection epilogue per residue ----------------
__global__ __launch_bounds__(128) void k_proj(const float* __restrict__ rot,
                                              const float* __restrict__ trans) {
  __shared__ float s2[24];
  int q = blockIdx.x, t = threadIdx.x;
  const float* lin = g_lin + q * LINW;
  if (t < 24) s2[t] = 0.f;
  __syncthreads();
  float R[9], tr[3];
#pragma unroll
  for (int j = 0; j < 9; ++j) R[j] = __ldg(rot + q * 9 + j);
#pragma unroll
  for (int j = 0; j < 3; ++j) tr[j] = __ldg(trans + q * 3 + j);
  for (int i = t; i < 192; i += 128) {
    int h = i >> 4, c = i & 15;
    g_qops[(h * N_ + q) * 32 + c] = (lin[i] + g_bpack[i]) * 0.25f;
    g_kops[(h * N_ + q) * 32 + c] = lin[192 + i] + g_bpack[192 + i];
    g_vops[(h * N_ + q) * 40 + c] = lin[384 + i] + g_bpack[384 + i];
  }
  if (t < 96) {
    int which = t / 48;
    int i = t % 48;
    int h = i >> 2, p = i & 3;
    int base = 576 + which * 144 + h * 12;
    float lx = lin[base + p] + g_bpack[base + p];
    float ly = lin[base + 4 + p] + g_bpack[base + 4 + p];
    float lz = lin[base + 8 + p] + g_bpack[base + 8 + p];
    float gx = R[0] * lx + R[1] * ly + R[2] * lz + tr[0];
    float gy = R[3] * lx + R[4] * ly + R[5] * lz + tr[1];
    float gz = R[6] * lx + R[7] * ly + R[8] * lz + tr[2];
    float n2 = gx * gx + gy * gy + gz * gz;
    int o = (h * N_ + q) * 32 + 16 + p * 3;
    if (which == 0) {
      g_qops[o] = gx; g_qops[o + 1] = gy; g_qops[o + 2] = gz;
      atomicAdd(&s2[h], n2);
    } else {
      g_kops[o] = gx; g_kops[o + 1] = gy; g_kops[o + 2] = gz;
      atomicAdd(&s2[12 + h], n2);
    }
  }
  if (t < 96) {
    int h = t >> 3, p = t & 7;
    int base = 864 + h * 24;
    float lx = lin[base + p] + g_bpack[base + p];
    float ly = lin[base + 8 + p] + g_bpack[base + 8 + p];
    float lz = lin[base + 16 + p] + g_bpack[base + 16 + p];
    float gx = R[0] * lx + R[1] * ly + R[2] * lz + tr[0];
    float gy = R[3] * lx + R[4] * ly + R[5] * lz + tr[1];
    float gz = R[6] * lx + R[7] * ly + R[8] * lz + tr[2];
    int o = (h * N_ + q) * 40 + 16 + p * 3;
    g_vops[o] = gx; g_vops[o + 1] = gy; g_vops[o + 2] = gz;
  }
  __syncthreads();
  if (t < 12) {
    g_qops[(t * N_ + q) * 32 + 28] = s2[t];
    g_kops[(t * N_ + q) * 32 + 28] = s2[12 + t];
  }
}

// ---------------- pair bias: k_bias9 — bias7 math, SINGLE z buffer (45KB => 2 blocks/SM) ----------------
// f32x2 lanes = row pair (r, r+256); 4 rows/thread; prefetch chunk in regs,
// store to smem only after all warps finish reading the previous chunk.
__global__ __launch_bounds__(128) void k_bias9(const float* __restrict__ z,
                                               const float* __restrict__ wb,
                                               const float* __restrict__ bb) {
  extern __shared__ u64 sm9[];
  u64* zb = sm9;                  // [16][257]
  u64* w2 = sm9 + 16 * 257;       // [128][12], each = pk2(w,w)
  int t = threadIdx.x;
  for (int idx = t; idx < 1536; idx += 128) {
    int c = idx / 12, h = idx - c * 12;
    float w = __ldg(wb + c * 12 + h);
    w2[idx] = pk2(w, w);
  }
  size_t R0 = (size_t)blockIdx.x * 512;

  float4 vA[8], vB[8];
  // load + store chunk 0
#pragma unroll
  for (int i = 0; i < 8; ++i) {
    int idx = t + i * 128;
    int rp = idx >> 2, j = idx & 3;
    const float* pA = z + (R0 + rp) * CZ + 4 * j;
    vA[i] = *(const float4*)pA;
    vB[i] = *(const float4*)(pA + 256 * CZ);
  }
#pragma unroll
  for (int i = 0; i < 8; ++i) {
    int idx = t + i * 128;
    int rp = idx >> 2, j = idx & 3;
    u64* d = zb + 4 * j * 257 + rp;
    d[0] = pk2(vA[i].x, vB[i].x);
    d[257] = pk2(vA[i].y, vB[i].y);
    d[514] = pk2(vA[i].z, vB[i].z);
    d[771] = pk2(vA[i].w, vB[i].w);
  }
  __syncthreads();

  u64 acc0[12] = {}, acc1[12] = {};
  for (int ch = 0; ch < 8; ++ch) {
    if (ch < 7) {
      // prefetch next chunk into registers; LDG latency hidden under compute
#pragma unroll
      for (int i = 0; i < 8; ++i) {
        int idx = t + i * 128;
        int rp = idx >> 2, j = idx & 3;
        const float* pA = z + (R0 + rp) * CZ + (ch + 1) * 16 + 4 * j;
        vA[i] = *(const float4*)pA;
        vB[i] = *(const float4*)(pA + 256 * CZ);
      }
    }
    const u64* w2c = w2 + ch * 16 * 12;
#pragma unroll
    for (int cl = 0; cl < 16; ++cl) {
      u64 z0 = zb[cl * 257 + t];
      u64 z1 = zb[cl * 257 + t + 128];
      const u64* wr = w2c + cl * 12;
#pragma unroll
      for (int h = 0; h < 12; ++h) {
        u64 w = wr[h];
        fma2(acc0[h], z0, w);
        fma2(acc1[h], z1, w);
      }
    }
    __syncthreads();   // all warps done reading zb
    if (ch < 7) {
#pragma unroll
      for (int i = 0; i < 8; ++i) {
        int idx = t + i * 128;
        int rp = idx >> 2, j = idx & 3;
        u64* d = zb + 4 * j * 257 + rp;
        d[0] = pk2(vA[i].x, vB[i].x);
        d[257] = pk2(vA[i].y, vB[i].y);
        d[514] = pk2(vA[i].z, vB[i].z);
        d[771] = pk2(vA[i].w, vB[i].w);
      }
      __syncthreads(); // zb refilled
    }
  }
#pragma unroll
  for (int h = 0; h < 12; ++h) {
    float bbh = __ldg(bb + h);
    float a, b, c, d;
    upk2(acc0[h], a, b);
    upk2(acc1[h], c, d);
    float* Lp = g_L + (size_t)h * NK_ + R0;
    Lp[t] = a + bbh;
    Lp[t + 256] = b + bbh;
    Lp[t + 128] = c + bbh;
    Lp[t + 384] = d + bbh;
  }
}

// ---------------- logits + softmax (in place on g_L) ----------------
__global__ __launch_bounds__(256) void k_logits(const float* __restrict__ mask) {
  __shared__ float ks[256 * 36];
  int t = threadIdx.x;
  int h = blockIdx.y;
  int Q0 = blockIdx.x * 16;
  int ql = t >> 4, s = t & 15;
  int q = Q0 + ql;
  const float* qop = g_qops + ((size_t)h * N_ + q) * 32;
  const u64* qop8 = (const u64*)qop;
  u64 qh_u[8], qp_u[6];
#pragma unroll
  for (int i = 0; i < 8; ++i) qh_u[i] = qop8[i];
#pragma unroll
  for (int i = 0; i < 6; ++i) qp_u[i] = qop8[8 + i];
  float q2 = qop[28];
  float pw = g_pw[h];
  float cb = -0.5f * pw * q2;
  float mq = __ldg(mask + q);
  const float* Lrow = g_L + ((size_t)h * N_ + q) * N_;
  float lg[48];
#pragma unroll
  for (int ch = 0; ch < 3; ++ch) {
    int k0 = ch * 256;
    __syncthreads();
#pragma unroll
    for (int i = 0; i < 8; ++i) {
      int idx = t + i * 256;
      int row = idx >> 3, f4 = idx & 7;
      *(float4*)(ks + row * 36 + f4 * 4) =
          *(const float4*)(g_kops + ((size_t)h * N_ + k0 + row) * 32 + f4 * 4);
    }
    __syncthreads();
#pragma unroll
    for (int jj = 0; jj < 16; ++jj) {
      int kl = s + 16 * jj;
      const u64* kr8 = (const u64*)(ks + kl * 36);
      u64 d2 = 0, e2 = 0;
#pragma unroll
      for (int i = 0; i < 8; ++i) fma2(d2, kr8[i], qh_u[i]);
#pragma unroll
      for (int i = 0; i < 6; ++i) fma2(e2, kr8[8 + i], qp_u[i]);
      float dlo, dhi, elo, ehi;
      upk2(d2, dlo, dhi);
      upk2(e2, elo, ehi);
      float k2s = ks[kl * 36 + 28];
      int k = k0 + kl;
      lg[ch * 16 + jj] = Lrow[k] + dlo + dhi + pw * (elo + ehi - 0.5f * k2s) + cb
                         + INF_ * (mq * __ldg(mask + k) - 1.f);
    }
  }
  float mx = -3.0e38f;
#pragma unroll
  for (int i = 0; i < 48; ++i) mx = fmaxf(mx, lg[i]);
  mx = fmaxf(mx, __shfl_xor_sync(0xffffffffu, mx, 1));
  mx = fmaxf(mx, __shfl_xor_sync(0xffffffffu, mx, 2));
  mx = fmaxf(mx, __shfl_xor_sync(0xffffffffu, mx, 4));
  mx = fmaxf(mx, __shfl_xor_sync(0xffffffffu, mx, 8));
  float sum = 0.f;
#pragma unroll
  for (int i = 0; i < 48; ++i) {
    float w = __expf(0.57735026919f * (lg[i] - mx));
    lg[i] = w;
    sum += w;
  }
  sum += __shfl_xor_sync(0xffffffffu, sum, 1);
  sum += __shfl_xor_sync(0xffffffffu, sum, 2);
  sum += __shfl_xor_sync(0xffffffffu, sum, 4);
  sum += __shfl_xor_sync(0xffffffffu, sum, 8);
  float inv = 1.f / sum;
  float* Lw = g_L + ((size_t)h * N_ + q) * N_;
#pragma unroll
  for (int ch = 0; ch < 3; ++ch)
#pragma unroll
    for (int jj = 0; jj < 16; ++jj)
      Lw[ch * 256 + s + 16 * jj] = lg[ch * 16 + jj] * inv;
}

// ---------------- o + o_pt + norms ----------------
__global__ __launch_bounds__(160) void k_out(const float* __restrict__ rot,
                                             const float* __restrict__ trans) {
  __shared__ float as[32 * 132];
  __shared__ float vs[128 * 44];
  __shared__ float os[32 * 40];
  int t = threadIdx.x;
  int h = blockIdx.y;
  int Q0 = blockIdx.x * 32;
  int q = t / 5, s = t - q * 5;
  u64 acc2[4] = {};
  for (int ch = 0; ch < 6; ++ch) {
    int k0 = ch * 128;
    __syncthreads();
    for (int idx = t; idx < 1024; idx += 160) {
      int qq = idx >> 5, f4 = idx & 31;
      *(float4*)(as + qq * 132 + f4 * 4) =
          *(const float4*)(g_L + ((size_t)h * N_ + Q0 + qq) * N_ + k0 + f4 * 4);
    }
    for (int idx = t; idx < 1280; idx += 160) {
      int row = idx / 10, f4 = idx - row * 10;
      *(float4*)(vs + row * 44 + f4 * 4) =
          *(const float4*)(g_vops + ((size_t)h * N_ + k0 + row) * 40 + f4 * 4);
    }
    __syncthreads();
#pragma unroll 4
    for (int kl = 0; kl < 128; ++kl) {
      float a = as[q * 132 + kl];
      u64 au = pk2(a, a);
      const u64* vp = (const u64*)(vs + kl * 44 + 8 * s);
      fma2(acc2[0], vp[0], au);
      fma2(acc2[1], vp[1], au);
      fma2(acc2[2], vp[2], au);
      fma2(acc2[3], vp[3], au);
    }
  }
#pragma unroll
  for (int i = 0; i < 4; ++i) {
    float lo, hi;
    upk2(acc2[i], lo, hi);
    os[q * 40 + 8 * s + 2 * i] = lo;
    os[q * 40 + 8 * s + 2 * i + 1] = hi;
  }
  __syncthreads();
  for (int idx = t; idx < 512; idx += 160) {
    int qq = idx >> 4, c = idx & 15;
    g_cat[(size_t)(Q0 + qq) * CATW + h * 16 + c] = os[qq * 40 + c];
  }
  for (int idx = t; idx < 256; idx += 160) {
    int qq = idx >> 3, p = idx & 7;
    int gq = Q0 + qq;
    float ex = os[qq * 40 + 16 + 3 * p] - __ldg(trans + gq * 3 + 0);
    float ey = os[qq * 40 + 17 + 3 * p] - __ldg(trans + gq * 3 + 1);
    float ez = os[qq * 40 + 18 + 3 * p] - __ldg(trans + gq * 3 + 2);
    const float* R = rot + gq * 9;
    float lx = __ldg(R + 0) * ex + __ldg(R + 3) * ey + __ldg(R + 6) * ez;
    float ly = __ldg(R + 1) * ex + __ldg(R + 4) * ey + __ldg(R + 7) * ez;
    float lz = __ldg(R + 2) * ex + __ldg(R + 5) * ey + __ldg(R + 8) * ez;
    float* cp = g_cat + (size_t)gq * CATW + 192 + h * 8 + p;
    cp[0] = lx;
    cp[96] = ly;
    cp[192] = lz;
    cp[288] = sqrtf(lx * lx + ly * ly + lz * lz + 1e-8f);
  }
}

// ---------------- o_pair (round-8 version — do not touch) ----------------
__global__ __launch_bounds__(256) void k_opair(const float* __restrict__ z) {
  extern __shared__ float sm[];
  float* aT = sm;  // [768][20]
  int t = threadIdx.x;
  int q = blockIdx.x;
#pragma unroll
  for (int h = 0; h < 12; ++h)
    for (int kk = t; kk < N_; kk += 256)
      aT[kk * 20 + h] = g_L[((size_t)h * N_ + q) * N_ + kk];
  __syncthreads();
  int c2 = (t & 63) * 2, kg = t >> 6;
  const float* zq = z + (size_t)q * N_ * CZ;
  u64 acc[12] = {};
#pragma unroll 4
  for (int k = kg; k < N_; k += 4) {
    u64 zd = *(const u64*)(zq + (size_t)k * CZ + c2);
    const float* ar = aT + k * 20;
    float4 a0 = *(const float4*)ar;
    float4 a1 = *(const float4*)(ar + 4);
    float4 a2 = *(const float4*)(ar + 8);
    float av[12] = {a0.x, a0.y, a0.z, a0.w, a1.x, a1.y, a1.z, a1.w,
                    a2.x, a2.y, a2.z, a2.w};
#pragma unroll
    for (int h = 0; h < 12; ++h) fma2(acc[h], zd, pk2(av[h], av[h]));
  }
  __syncthreads();
  u64* buf = (u64*)sm;  // [256][12]
#pragma unroll
  for (int h = 0; h < 12; ++h) buf[t * 12 + h] = acc[h];
  __syncthreads();
  for (int idx = t; idx < 1536; idx += 256) {
    int h = idx >> 7, c = idx & 127;
    float sum = 0.f;
#pragma unroll
    for (int g = 0; g < 4; ++g) {
      float lo, hi;
      upk2(buf[(g * 64 + (c >> 1)) * 12 + h], lo, hi);
      sum += (c & 1) ? hi : lo;
    }
    g_cat[(size_t)q * CATW + 576 + h * 128 + c] = sum;
  }
}

// ---------------- final add ----------------
__global__ void k_add(const float* __restrict__ bo, float* __restrict__ out) {
  int i = blockIdx.x * 256 + threadIdx.x;
  if (i < N_ * CS) {
    int col = i % CS;
    out[i] = g_part[0][i] + g_part[1][i] + g_part[2][i] + __ldg(bo + col);
  }
}

extern "C" void kernel_launch(void* const* d_in, const int* in_sizes, int n_in,
                              void* d_out, int out_size) {
  const float* s     = (const float*)d_in[0];
  const float* z     = (const float*)d_in[1];
  const float* rot   = (const float*)d_in[2];
  const float* trans = (const float*)d_in[3];
  const float* mask  = (const float*)d_in[4];
  const float* w_q   = (const float*)d_in[5];
  const float* b_q   = (const float*)d_in[6];
  const float* w_k   = (const float*)d_in[7];
  const float* b_k   = (const float*)d_in[8];
  const float* w_v   = (const float*)d_in[9];
  const float* b_v   = (const float*)d_in[10];
  const float* w_qp  = (const float*)d_in[11];
  const float* b_qp  = (const float*)d_in[12];
  const float* w_kp  = (const float*)d_in[13];
  const float* b_kp  = (const float*)d_in[14];
  const float* w_vp  = (const float*)d_in[15];
  const float* b_vp  = (const float*)d_in[16];
  const float* w_b   = (const float*)d_in[17];
  const float* b_b   = (const float*)d_in[18];
  const float* hw    = (const float*)d_in[19];
  const float* w_o   = (const float*)d_in[20];
  const float* b_o   = (const float*)d_in[21];
  float* out = (float*)d_out;

  const int BIAS_SMEM = (16 * 257 + 1536) * 8;  // 45184 bytes

  static bool init_done = false;
  static cudaStream_t s2, s3;
  static cudaEvent_t e_fork1, e_join1, e_fork2, e_j2, e_fork3, e_c;
  if (!init_done) {
    cudaFuncSetAttribute(k_opair, cudaFuncAttributeMaxDynamicSharedMemorySize, 65536);
    cudaFuncSetAttribute(k_bias9, cudaFuncAttributeMaxDynamicSharedMemorySize, BIAS_SMEM);
    cudaStreamCreateWithFlags(&s2, cudaStreamNonBlocking);
    cudaStreamCreateWithFlags(&s3, cudaStreamNonBlocking);
    cudaEventCreateWithFlags(&e_fork1, cudaEventDisableTiming);
    cudaEventCreateWithFlags(&e_join1, cudaEventDisableTiming);
    cudaEventCreateWithFlags(&e_fork2, cudaEventDisableTiming);
    cudaEventCreateWithFlags(&e_j2, cudaEventDisableTiming);
    cudaEventCreateWithFlags(&e_fork3, cudaEventDisableTiming);
    cudaEventCreateWithFlags(&e_c, cudaEventDisableTiming);
    init_done = true;
  }

  // Fork 1: bias (memory path) on s2; projections (compute path) on default.
  cudaEventRecord(e_fork1, 0);
  cudaStreamWaitEvent(s2, e_fork1, 0);
  k_bias9<<<1152, 128, BIAS_SMEM, s2>>>(z, w_b, b_b);
  cudaEventRecord(e_join1, s2);

  k_pack<<<1728, 256>>>(w_q, w_k, w_v, w_qp, w_kp, w_vp,
                        b_q, b_k, b_v, b_qp, b_kp, b_vp, hw);
  k_gemm1<<<dim3(12, 18), 256>>>(s);
  k_proj<<<N_, 128>>>(rot, trans);
  cudaStreamWaitEvent(0, e_join1, 0);

  k_logits<<<dim3(48, 12), 256>>>(mask);

  // Fork 2: k_opair on s2 concurrent with k_out + gemm2 part A on default.
  cudaEventRecord(e_fork2, 0);
  cudaStreamWaitEvent(s2, e_fork2, 0);
  k_opair<<<N_, 256, 768 * 20 * 4, s2>>>(z);
  cudaEventRecord(e_j2, s2);

  k_out<<<dim3(24, 12), 160>>>(rot, trans);
  // Part A reads g_cat cols [0,576) — produced only by k_out; overlaps k_opair.
  k_gemm2<<<dim3(12, 6), 256>>>(w_o, 0, 36, 0);

  // Parts B and C read cols [576,2112) — produced by k_opair. Run B ∥ C.
  cudaStreamWaitEvent(0, e_j2, 0);
  cudaEventRecord(e_fork3, 0);
  cudaStreamWaitEvent(s3, e_fork3, 0);
  k_gemm2<<<dim3(12, 6), 256, 0, s3>>>(w_o, 84, 48, 2);
  cudaEventRecord(e_c, s3);

  k_gemm2<<<dim3(12, 6), 256>>>(w_o, 36, 48, 1);
  cudaStreamWaitEvent(0, e_c, 0);
  k_add<<<1152, 256>>>(b_o, out);
}